// round 1
// baseline (speedup 1.0000x reference)
#include <cuda_runtime.h>
#include <math.h>

// ---------------- problem constants ----------------
#define NNODE 1000
#define NPAD  1024
#define BATCH 32
#define SEQ   48
#define HID   64
#define FEATD 40
#define XCOLS (SEQ*BATCH*FEATD)   // 61440
#define HCOLS (BATCH*HID)         // 2048
#define KIN   104                 // FEATD + HID

// ---------------- static device scratch (no allocation allowed) ----------------
__device__ __align__(128) float g_L   [NPAD * NPAD];
__device__                float g_dis [NPAD];
__device__ __align__(128) float g_xT  [NPAD * XCOLS];   // x,  layout [node][s*1280 + b*40 + f]
__device__ __align__(128) float g_LxT [NPAD * XCOLS];   // L@x
__device__ __align__(128) float g_hT  [NPAD * HCOLS];   // h,   [node][b*64 + c]
__device__ __align__(128) float g_LhT [NPAD * HCOLS];
__device__ __align__(128) float g_rhT [NPAD * HCOLS];   // r*h
__device__ __align__(128) float g_LrhT[NPAD * HCOLS];
__device__ __align__(128) float g_uT  [NPAD * HCOLS];   // update gate (already remapped)

// ---------------- init / zero ----------------
__global__ void k_zero_state() {
    int i = blockIdx.x * blockDim.x + threadIdx.x;
    if (i < NPAD * HCOLS) {
        g_hT[i] = 0.f;
        if (i >= NNODE * HCOLS) g_rhT[i] = 0.f;   // keep K-pad rows of rhT zero
    }
}
__global__ void k_zero_xpad() {
    int i = blockIdx.x * blockDim.x + threadIdx.x;
    int tot = (NPAD - NNODE) * XCOLS;
    if (i < tot) g_xT[NNODE * XCOLS + i] = 0.f;
}

// ---------------- Laplacian ----------------
__global__ void k_rowsum(const float* __restrict__ adj) {
    int m = blockIdx.x;            // 0..999
    int tid = threadIdx.x;
    float s = 0.f;
    for (int k = tid; k < NNODE; k += 256) s += adj[m * NNODE + k];
    __shared__ float sm[256];
    sm[tid] = s; __syncthreads();
    for (int st = 128; st > 0; st >>= 1) {
        if (tid < st) sm[tid] += sm[tid + st];
        __syncthreads();
    }
    if (tid == 0) g_dis[m] = rsqrtf(sm[0] + 1.0f);   // +1 for self loop
}
__global__ void k_buildL(const float* __restrict__ adj) {
    int i = blockIdx.x * blockDim.x + threadIdx.x;
    if (i >= NPAD * NPAD) return;
    int m = i >> 10, n = i & (NPAD - 1);
    float v = 0.f;
    if (m < NNODE && n < NNODE) {
        float a = adj[m * NNODE + n] + (m == n ? 1.f : 0.f);
        v = g_dis[m] * a * g_dis[n];
    }
    g_L[i] = v;
}

// ---------------- aspect projections -> xT ----------------
__global__ void k_aspect(const float* __restrict__ inp,
                         const float* __restrict__ Wo, const float* __restrict__ bo,
                         const float* __restrict__ Wd, const float* __restrict__ bd,
                         const float* __restrict__ We, const float* __restrict__ be,
                         const float* __restrict__ Wi, const float* __restrict__ bi) {
    int i = blockIdx.x * blockDim.x + threadIdx.x;
    if (i >= NNODE * XCOLS) return;
    int n   = i / XCOLS;
    int col = i - n * XCOLS;
    int s   = col / (BATCH * FEATD);
    int rem = col - s * (BATCH * FEATD);
    int b   = rem / FEATD;
    int f   = rem - b * FEATD;
    const float* base = inp + (((size_t)(b * SEQ + s) * NNODE + n) * 21);
    int fo = f % 10;
    float acc;
    if (f < 10) {
        const int idx[5] = {2, 5, 8, 9, 12};
        acc = __ldg(bo + fo);
        #pragma unroll
        for (int j = 0; j < 5; j++) acc += __ldg(base + idx[j]) * __ldg(Wo + j * 10 + fo);
    } else if (f < 20) {
        const int idx[3] = {10, 14, 15};
        acc = __ldg(bd + fo);
        #pragma unroll
        for (int j = 0; j < 3; j++) acc += __ldg(base + idx[j]) * __ldg(Wd + j * 10 + fo);
    } else if (f < 30) {
        const int idx[2] = {13, 17};
        acc = __ldg(be + fo);
        #pragma unroll
        for (int j = 0; j < 2; j++) acc += __ldg(base + idx[j]) * __ldg(We + j * 10 + fo);
    } else {
        const int idx[2] = {19, 20};
        acc = __ldg(bi + fo);
        #pragma unroll
        for (int j = 0; j < 2; j++) acc += __ldg(base + idx[j]) * __ldg(Wi + j * 10 + fo);
    }
    g_xT[n * XCOLS + col] = acc;
}

// ---------------- fp32 SGEMM: C[M,N] = A[M,K] @ B[K,N]; all dims multiples of tile ----------------
#define BM 128
#define BN 128
#define BK 8
#define TM 8
#define TN 8
__global__ __launch_bounds__(256, 2)
void sgemm(const float* __restrict__ A, const float* __restrict__ B,
           float* __restrict__ C, int M, int N, int K) {
    __shared__ float As[BK][BM];
    __shared__ float Bs[BK][BN];
    int tid = threadIdx.x;
    int bx = blockIdx.x;   // N dim
    int by = blockIdx.y;   // M dim
    const float* Ab = A + (size_t)by * BM * K;
    const float* Bb = B + (size_t)bx * BN;
    int aRow = tid >> 1;          // 0..127
    int aCol = (tid & 1) * 4;     // 0 or 4
    int bRow = tid >> 5;          // 0..7
    int bCol = (tid & 31) * 4;    // 0..124
    int tx = tid & 15, ty = tid >> 4;
    float acc[TM][TN] = {};
    for (int k0 = 0; k0 < K; k0 += BK) {
        float4 a4 = *(const float4*)(Ab + (size_t)aRow * K + k0 + aCol);
        float4 b4 = *(const float4*)(Bb + (size_t)(k0 + bRow) * N + bCol);
        As[aCol + 0][aRow] = a4.x; As[aCol + 1][aRow] = a4.y;
        As[aCol + 2][aRow] = a4.z; As[aCol + 3][aRow] = a4.w;
        *(float4*)&Bs[bRow][bCol] = b4;
        __syncthreads();
        #pragma unroll
        for (int k = 0; k < BK; ++k) {
            float ar[TM], br[TN];
            #pragma unroll
            for (int i = 0; i < TM; i++) ar[i] = As[k][ty * TM + i];
            #pragma unroll
            for (int j = 0; j < TN; j++) br[j] = Bs[k][tx * TN + j];
            #pragma unroll
            for (int i = 0; i < TM; i++)
                #pragma unroll
                for (int j = 0; j < TN; j++)
                    acc[i][j] += ar[i] * br[j];
        }
        __syncthreads();
    }
    float* Cb = C + (size_t)(by * BM + ty * TM) * N + bx * BN + tx * TN;
    #pragma unroll
    for (int i = 0; i < TM; i++) {
        *(float4*)(Cb + (size_t)i * N)     = make_float4(acc[i][0], acc[i][1], acc[i][2], acc[i][3]);
        *(float4*)(Cb + (size_t)i * N + 4) = make_float4(acc[i][4], acc[i][5], acc[i][6], acc[i][7]);
    }
}

// ---------------- gate kernel: ru = sigmoid([Lx|Lh] @ W1 + b1), fused chunk-scatter ----------------
// grid.y selects output half (0 -> cols 0..63, 1 -> cols 64..127)
__global__ __launch_bounds__(256)
void k_gate(const float* __restrict__ W1, const float* __restrict__ b1, int t) {
    __shared__ float Ws[KIN * 64];
    __shared__ float bs[64];
    int half = blockIdx.y;
    for (int i = threadIdx.x; i < KIN * 64; i += 256)
        Ws[i] = W1[(i >> 6) * 128 + half * 64 + (i & 63)];
    if (threadIdx.x < 64) bs[threadIdx.x] = b1[half * 64 + threadIdx.x];
    __syncthreads();
    int lane = threadIdx.x & 31;
    int warp = threadIdx.x >> 5;
    for (int r = 0; r < 8; ++r) {
        int row = (blockIdx.x * 8 + warp) + r * 4000;  // 0..31999
        int n = row >> 5;     // node 0..999
        int b = row & 31;
        const float* lx = g_LxT + n * XCOLS + t * (BATCH * FEATD) + b * FEATD;
        const float* lh = g_LhT + n * HCOLS + b * HID;
        float v0 = lx[lane];
        float v1 = (lane < 8) ? lx[32 + lane] : lh[lane - 8];
        float v2 = lh[24 + lane];
        float v3 = (lane < 8) ? lh[56 + lane] : 0.f;
        float a0 = bs[lane], a1 = bs[lane + 32];
        #pragma unroll
        for (int k = 0; k < KIN; ++k) {
            float src = (k < 32) ? v0 : (k < 64) ? v1 : (k < 96) ? v2 : v3;
            float val = __shfl_sync(0xffffffffu, src, k & 31);
            a0 += val * Ws[k * 64 + lane];
            a1 += val * Ws[k * 64 + lane + 32];
        }
        float s0 = 1.f / (1.f + expf(-a0));
        float s1 = 1.f / (1.f + expf(-a1));
        if (n < 500) {
            // r-gate: multiplies h at remapped rows nh = 2n + half
            int o = (2 * n + half) * HCOLS + b * HID;
            g_rhT[o + lane]      = g_hT[o + lane]      * s0;
            g_rhT[o + lane + 32] = g_hT[o + lane + 32] * s1;
        } else {
            // u-gate for rows nh = 2*(n-500) + half
            int o = (2 * (n - 500) + half) * HCOLS + b * HID;
            g_uT[o + lane]      = s0;
            g_uT[o + lane + 32] = s1;
        }
    }
}

// ---------------- candidate + GRU update: c = tanh([Lx|Lrh] @ W2 + b2); h = u*h + (1-u)*c ----------------
__global__ __launch_bounds__(256)
void k_cand(const float* __restrict__ W2, const float* __restrict__ b2, int t) {
    __shared__ float Ws[KIN * 64];
    __shared__ float bs[64];
    for (int i = threadIdx.x; i < KIN * 64; i += 256) Ws[i] = W2[i];
    if (threadIdx.x < 64) bs[threadIdx.x] = b2[threadIdx.x];
    __syncthreads();
    int lane = threadIdx.x & 31;
    int warp = threadIdx.x >> 5;
    for (int r = 0; r < 8; ++r) {
        int row = (blockIdx.x * 8 + warp) + r * 4000;
        int n = row >> 5;
        int b = row & 31;
        const float* lx  = g_LxT  + n * XCOLS + t * (BATCH * FEATD) + b * FEATD;
        const float* lrh = g_LrhT + n * HCOLS + b * HID;
        float v0 = lx[lane];
        float v1 = (lane < 8) ? lx[32 + lane] : lrh[lane - 8];
        float v2 = lrh[24 + lane];
        float v3 = (lane < 8) ? lrh[56 + lane] : 0.f;
        float a0 = bs[lane], a1 = bs[lane + 32];
        #pragma unroll
        for (int k = 0; k < KIN; ++k) {
            float src = (k < 32) ? v0 : (k < 64) ? v1 : (k < 96) ? v2 : v3;
            float val = __shfl_sync(0xffffffffu, src, k & 31);
            a0 += val * Ws[k * 64 + lane];
            a1 += val * Ws[k * 64 + lane + 32];
        }
        float c0 = tanhf(a0);
        float c1 = tanhf(a1);
        int o = n * HCOLS + b * HID;
        float u0 = g_uT[o + lane], u1 = g_uT[o + lane + 32];
        float h0 = g_hT[o + lane], h1 = g_hT[o + lane + 32];
        g_hT[o + lane]      = u0 * h0 + (1.f - u0) * c0;
        g_hT[o + lane + 32] = u1 * h1 + (1.f - u1) * c1;
    }
}

// ---------------- final transpose to [B, N, H] ----------------
__global__ void k_out(float* __restrict__ out) {
    int i = blockIdx.x * blockDim.x + threadIdx.x;
    if (i >= BATCH * NNODE * HID) return;
    int ch = i & (HID - 1);
    int n  = (i >> 6) % NNODE;
    int b  = i / (NNODE * HID);
    out[i] = g_hT[n * HCOLS + b * HID + ch];
}

// ---------------- launcher ----------------
extern "C" void kernel_launch(void* const* d_in, const int* in_sizes, int n_in,
                              void* d_out, int out_size) {
    const float* inp = (const float*)d_in[0];
    const float* adj = (const float*)d_in[1];
    const float* Wo  = (const float*)d_in[2];  const float* bo = (const float*)d_in[3];
    const float* Wd  = (const float*)d_in[4];  const float* bd = (const float*)d_in[5];
    const float* We  = (const float*)d_in[6];  const float* be = (const float*)d_in[7];
    const float* Wi  = (const float*)d_in[8];  const float* bi = (const float*)d_in[9];
    const float* W1  = (const float*)d_in[10]; const float* b1 = (const float*)d_in[11];
    const float* W2  = (const float*)d_in[12]; const float* b2 = (const float*)d_in[13];
    float* out = (float*)d_out;

    float *L, *xT, *LxT, *hT, *rhT;
    cudaGetSymbolAddress((void**)&L,   g_L);
    cudaGetSymbolAddress((void**)&xT,  g_xT);
    cudaGetSymbolAddress((void**)&LxT, g_LxT);
    cudaGetSymbolAddress((void**)&hT,  g_hT);
    cudaGetSymbolAddress((void**)&rhT, g_rhT);
    float *LhT, *LrhT;
    cudaGetSymbolAddress((void**)&LhT,  g_LhT);
    cudaGetSymbolAddress((void**)&LrhT, g_LrhT);

    // reset recurrent state (graph replays reuse static scratch)
    k_zero_state<<<(NPAD * HCOLS + 255) / 256, 256>>>();
    k_zero_xpad <<<((NPAD - NNODE) * XCOLS + 255) / 256, 256>>>();

    // Laplacian
    k_rowsum<<<NNODE, 256>>>(adj);
    k_buildL<<<(NPAD * NPAD) / 256, 256>>>(adj);

    // aspect projections for all (b,s,n)
    k_aspect<<<(NNODE * XCOLS + 255) / 256, 256>>>(inp, Wo, bo, Wd, bd, We, be, Wi, bi);

    // hoisted graph aggregation of x for ALL timesteps: LxT = L @ xT  (129 GFLOP, one GEMM)
    sgemm<<<dim3(XCOLS / BN, NPAD / BM), 256>>>(L, xT, LxT, NPAD, XCOLS, NPAD);

    // recurrent scan
    for (int t = 0; t < SEQ; ++t) {
        sgemm<<<dim3(HCOLS / BN, NPAD / BM), 256>>>(L, hT, LhT, NPAD, HCOLS, NPAD);
        k_gate<<<dim3(500, 2), 256>>>(W1, b1, t);
        sgemm<<<dim3(HCOLS / BN, NPAD / BM), 256>>>(L, rhT, LrhT, NPAD, HCOLS, NPAD);
        k_cand<<<500, 256>>>(W2, b2, t);
    }

    k_out<<<(BATCH * NNODE * HID + 255) / 256, 256>>>(out);
}

// round 2
// speedup vs baseline: 1.0014x; 1.0014x over previous
#include <cuda_runtime.h>
#include <math.h>

// ---------------- problem constants ----------------
#define NNODE 1000
#define NPAD  1024
#define BATCH 32
#define SEQ   48
#define HID   64
#define FEATD 40
#define XCOLS (SEQ*BATCH*FEATD)   // 61440
#define HCOLS (BATCH*HID)         // 2048
#define KIN   104                 // FEATD + HID

// ---------------- static device scratch (no allocation allowed) ----------------
__device__ __align__(128) float g_L   [NPAD * NPAD];
__device__                float g_dis [NPAD];
__device__ __align__(128) float g_xT  [NPAD * XCOLS];   // x,  layout [node][s*1280 + b*40 + f]
__device__ __align__(128) float g_LxT [NPAD * XCOLS];   // L@x
__device__ __align__(128) float g_hT  [NPAD * HCOLS];   // h,   [node][b*64 + c]
__device__ __align__(128) float g_LhT [NPAD * HCOLS];
__device__ __align__(128) float g_rhT [NPAD * HCOLS];   // r*h
__device__ __align__(128) float g_LrhT[NPAD * HCOLS];
__device__ __align__(128) float g_uT  [NPAD * HCOLS];   // update gate (already remapped)

// ---------------- init / zero ----------------
__global__ void k_zero_state() {
    int i = blockIdx.x * blockDim.x + threadIdx.x;
    if (i < NPAD * HCOLS) {
        g_hT[i] = 0.f;
        if (i >= NNODE * HCOLS) g_rhT[i] = 0.f;   // keep K-pad rows of rhT zero
    }
}
__global__ void k_zero_xpad() {
    int i = blockIdx.x * blockDim.x + threadIdx.x;
    int tot = (NPAD - NNODE) * XCOLS;
    if (i < tot) g_xT[NNODE * XCOLS + i] = 0.f;
}

// ---------------- Laplacian ----------------
__global__ void k_rowsum(const float* __restrict__ adj) {
    int m = blockIdx.x;            // 0..999
    int tid = threadIdx.x;
    float s = 0.f;
    for (int k = tid; k < NNODE; k += 256) s += adj[m * NNODE + k];
    __shared__ float sm[256];
    sm[tid] = s; __syncthreads();
    for (int st = 128; st > 0; st >>= 1) {
        if (tid < st) sm[tid] += sm[tid + st];
        __syncthreads();
    }
    if (tid == 0) g_dis[m] = rsqrtf(sm[0] + 1.0f);   // +1 for self loop
}
__global__ void k_buildL(const float* __restrict__ adj) {
    int i = blockIdx.x * blockDim.x + threadIdx.x;
    if (i >= NPAD * NPAD) return;
    int m = i >> 10, n = i & (NPAD - 1);
    float v = 0.f;
    if (m < NNODE && n < NNODE) {
        float a = adj[m * NNODE + n] + (m == n ? 1.f : 0.f);
        v = g_dis[m] * a * g_dis[n];
    }
    g_L[i] = v;
}

// ---------------- aspect projections -> xT ----------------
__global__ void k_aspect(const float* __restrict__ inp,
                         const float* __restrict__ Wo, const float* __restrict__ bo,
                         const float* __restrict__ Wd, const float* __restrict__ bd,
                         const float* __restrict__ We, const float* __restrict__ be,
                         const float* __restrict__ Wi, const float* __restrict__ bi) {
    int i = blockIdx.x * blockDim.x + threadIdx.x;
    if (i >= NNODE * XCOLS) return;
    int n   = i / XCOLS;
    int col = i - n * XCOLS;
    int s   = col / (BATCH * FEATD);
    int rem = col - s * (BATCH * FEATD);
    int b   = rem / FEATD;
    int f   = rem - b * FEATD;
    const float* base = inp + (((size_t)(b * SEQ + s) * NNODE + n) * 21);
    int fo = f % 10;
    float acc;
    if (f < 10) {
        const int idx[5] = {2, 5, 8, 9, 12};
        acc = __ldg(bo + fo);
        #pragma unroll
        for (int j = 0; j < 5; j++) acc += __ldg(base + idx[j]) * __ldg(Wo + j * 10 + fo);
    } else if (f < 20) {
        const int idx[3] = {10, 14, 15};
        acc = __ldg(bd + fo);
        #pragma unroll
        for (int j = 0; j < 3; j++) acc += __ldg(base + idx[j]) * __ldg(Wd + j * 10 + fo);
    } else if (f < 30) {
        const int idx[2] = {13, 17};
        acc = __ldg(be + fo);
        #pragma unroll
        for (int j = 0; j < 2; j++) acc += __ldg(base + idx[j]) * __ldg(We + j * 10 + fo);
    } else {
        const int idx[2] = {19, 20};
        acc = __ldg(bi + fo);
        #pragma unroll
        for (int j = 0; j < 2; j++) acc += __ldg(base + idx[j]) * __ldg(Wi + j * 10 + fo);
    }
    g_xT[n * XCOLS + col] = acc;
}

// ---------------- fp32 SGEMM: C[M,N] = A[M,K] @ B[K,N]; all dims multiples of tile ----------------
#define BM 128
#define BN 128
#define BK 8
#define TM 8
#define TN 8
__global__ __launch_bounds__(256, 2)
void sgemm(const float* __restrict__ A, const float* __restrict__ B,
           float* __restrict__ C, int M, int N, int K) {
    __shared__ float As[BK][BM];
    __shared__ float Bs[BK][BN];
    int tid = threadIdx.x;
    int bx = blockIdx.x;   // N dim
    int by = blockIdx.y;   // M dim
    const float* Ab = A + (size_t)by * BM * K;
    const float* Bb = B + (size_t)bx * BN;
    int aRow = tid >> 1;          // 0..127
    int aCol = (tid & 1) * 4;     // 0 or 4
    int bRow = tid >> 5;          // 0..7
    int bCol = (tid & 31) * 4;    // 0..124
    int tx = tid & 15, ty = tid >> 4;
    float acc[TM][TN] = {};
    for (int k0 = 0; k0 < K; k0 += BK) {
        float4 a4 = *(const float4*)(Ab + (size_t)aRow * K + k0 + aCol);
        float4 b4 = *(const float4*)(Bb + (size_t)(k0 + bRow) * N + bCol);
        As[aCol + 0][aRow] = a4.x; As[aCol + 1][aRow] = a4.y;
        As[aCol + 2][aRow] = a4.z; As[aCol + 3][aRow] = a4.w;
        *(float4*)&Bs[bRow][bCol] = b4;
        __syncthreads();
        #pragma unroll
        for (int k = 0; k < BK; ++k) {
            float ar[TM], br[TN];
            #pragma unroll
            for (int i = 0; i < TM; i++) ar[i] = As[k][ty * TM + i];
            #pragma unroll
            for (int j = 0; j < TN; j++) br[j] = Bs[k][tx * TN + j];
            #pragma unroll
            for (int i = 0; i < TM; i++)
                #pragma unroll
                for (int j = 0; j < TN; j++)
                    acc[i][j] += ar[i] * br[j];
        }
        __syncthreads();
    }
    float* Cb = C + (size_t)(by * BM + ty * TM) * N + bx * BN + tx * TN;
    #pragma unroll
    for (int i = 0; i < TM; i++) {
        *(float4*)(Cb + (size_t)i * N)     = make_float4(acc[i][0], acc[i][1], acc[i][2], acc[i][3]);
        *(float4*)(Cb + (size_t)i * N + 4) = make_float4(acc[i][4], acc[i][5], acc[i][6], acc[i][7]);
    }
}

// ---------------- gate kernel: ru = sigmoid([Lx|Lh] @ W1 + b1), fused chunk-scatter ----------------
// grid.y selects output half (0 -> cols 0..63, 1 -> cols 64..127)
__global__ __launch_bounds__(256)
void k_gate(const float* __restrict__ W1, const float* __restrict__ b1, int t) {
    __shared__ float Ws[KIN * 64];
    __shared__ float bs[64];
    int half = blockIdx.y;
    for (int i = threadIdx.x; i < KIN * 64; i += 256)
        Ws[i] = W1[(i >> 6) * 128 + half * 64 + (i & 63)];
    if (threadIdx.x < 64) bs[threadIdx.x] = b1[half * 64 + threadIdx.x];
    __syncthreads();
    int lane = threadIdx.x & 31;
    int warp = threadIdx.x >> 5;
    for (int r = 0; r < 8; ++r) {
        int row = (blockIdx.x * 8 + warp) + r * 4000;  // 0..31999
        int n = row >> 5;     // node 0..999
        int b = row & 31;
        const float* lx = g_LxT + n * XCOLS + t * (BATCH * FEATD) + b * FEATD;
        const float* lh = g_LhT + n * HCOLS + b * HID;
        float v0 = lx[lane];
        float v1 = (lane < 8) ? lx[32 + lane] : lh[lane - 8];
        float v2 = lh[24 + lane];
        float v3 = (lane < 8) ? lh[56 + lane] : 0.f;
        float a0 = bs[lane], a1 = bs[lane + 32];
        #pragma unroll
        for (int k = 0; k < KIN; ++k) {
            float src = (k < 32) ? v0 : (k < 64) ? v1 : (k < 96) ? v2 : v3;
            float val = __shfl_sync(0xffffffffu, src, k & 31);
            a0 += val * Ws[k * 64 + lane];
            a1 += val * Ws[k * 64 + lane + 32];
        }
        float s0 = 1.f / (1.f + expf(-a0));
        float s1 = 1.f / (1.f + expf(-a1));
        if (n < 500) {
            // r-gate: multiplies h at remapped rows nh = 2n + half
            int o = (2 * n + half) * HCOLS + b * HID;
            g_rhT[o + lane]      = g_hT[o + lane]      * s0;
            g_rhT[o + lane + 32] = g_hT[o + lane + 32] * s1;
        } else {
            // u-gate for rows nh = 2*(n-500) + half
            int o = (2 * (n - 500) + half) * HCOLS + b * HID;
            g_uT[o + lane]      = s0;
            g_uT[o + lane + 32] = s1;
        }
    }
}

// ---------------- candidate + GRU update: c = tanh([Lx|Lrh] @ W2 + b2); h = u*h + (1-u)*c ----------------
__global__ __launch_bounds__(256)
void k_cand(const float* __restrict__ W2, const float* __restrict__ b2, int t) {
    __shared__ float Ws[KIN * 64];
    __shared__ float bs[64];
    for (int i = threadIdx.x; i < KIN * 64; i += 256) Ws[i] = W2[i];
    if (threadIdx.x < 64) bs[threadIdx.x] = b2[threadIdx.x];
    __syncthreads();
    int lane = threadIdx.x & 31;
    int warp = threadIdx.x >> 5;
    for (int r = 0; r < 8; ++r) {
        int row = (blockIdx.x * 8 + warp) + r * 4000;
        int n = row >> 5;
        int b = row & 31;
        const float* lx  = g_LxT  + n * XCOLS + t * (BATCH * FEATD) + b * FEATD;
        const float* lrh = g_LrhT + n * HCOLS + b * HID;
        float v0 = lx[lane];
        float v1 = (lane < 8) ? lx[32 + lane] : lrh[lane - 8];
        float v2 = lrh[24 + lane];
        float v3 = (lane < 8) ? lrh[56 + lane] : 0.f;
        float a0 = bs[lane], a1 = bs[lane + 32];
        #pragma unroll
        for (int k = 0; k < KIN; ++k) {
            float src = (k < 32) ? v0 : (k < 64) ? v1 : (k < 96) ? v2 : v3;
            float val = __shfl_sync(0xffffffffu, src, k & 31);
            a0 += val * Ws[k * 64 + lane];
            a1 += val * Ws[k * 64 + lane + 32];
        }
        float c0 = tanhf(a0);
        float c1 = tanhf(a1);
        int o = n * HCOLS + b * HID;
        float u0 = g_uT[o + lane], u1 = g_uT[o + lane + 32];
        float h0 = g_hT[o + lane], h1 = g_hT[o + lane + 32];
        g_hT[o + lane]      = u0 * h0 + (1.f - u0) * c0;
        g_hT[o + lane + 32] = u1 * h1 + (1.f - u1) * c1;
    }
}

// ---------------- final transpose to [B, N, H] ----------------
__global__ void k_out(float* __restrict__ out) {
    int i = blockIdx.x * blockDim.x + threadIdx.x;
    if (i >= BATCH * NNODE * HID) return;
    int ch = i & (HID - 1);
    int n  = (i >> 6) % NNODE;
    int b  = i / (NNODE * HID);
    out[i] = g_hT[n * HCOLS + b * HID + ch];
}

// ---------------- launcher ----------------
extern "C" void kernel_launch(void* const* d_in, const int* in_sizes, int n_in,
                              void* d_out, int out_size) {
    const float* inp = (const float*)d_in[0];
    const float* adj = (const float*)d_in[1];
    const float* Wo  = (const float*)d_in[2];  const float* bo = (const float*)d_in[3];
    const float* Wd  = (const float*)d_in[4];  const float* bd = (const float*)d_in[5];
    const float* We  = (const float*)d_in[6];  const float* be = (const float*)d_in[7];
    const float* Wi  = (const float*)d_in[8];  const float* bi = (const float*)d_in[9];
    const float* W1  = (const float*)d_in[10]; const float* b1 = (const float*)d_in[11];
    const float* W2  = (const float*)d_in[12]; const float* b2 = (const float*)d_in[13];
    float* out = (float*)d_out;

    float *L, *xT, *LxT, *hT, *rhT;
    cudaGetSymbolAddress((void**)&L,   g_L);
    cudaGetSymbolAddress((void**)&xT,  g_xT);
    cudaGetSymbolAddress((void**)&LxT, g_LxT);
    cudaGetSymbolAddress((void**)&hT,  g_hT);
    cudaGetSymbolAddress((void**)&rhT, g_rhT);
    float *LhT, *LrhT;
    cudaGetSymbolAddress((void**)&LhT,  g_LhT);
    cudaGetSymbolAddress((void**)&LrhT, g_LrhT);

    // reset recurrent state (graph replays reuse static scratch)
    k_zero_state<<<(NPAD * HCOLS + 255) / 256, 256>>>();
    k_zero_xpad <<<((NPAD - NNODE) * XCOLS + 255) / 256, 256>>>();

    // Laplacian
    k_rowsum<<<NNODE, 256>>>(adj);
    k_buildL<<<(NPAD * NPAD) / 256, 256>>>(adj);

    // aspect projections for all (b,s,n)
    k_aspect<<<(NNODE * XCOLS + 255) / 256, 256>>>(inp, Wo, bo, Wd, bd, We, be, Wi, bi);

    // hoisted graph aggregation of x for ALL timesteps: LxT = L @ xT  (129 GFLOP, one GEMM)
    sgemm<<<dim3(XCOLS / BN, NPAD / BM), 256>>>(L, xT, LxT, NPAD, XCOLS, NPAD);

    // recurrent scan
    for (int t = 0; t < SEQ; ++t) {
        sgemm<<<dim3(HCOLS / BN, NPAD / BM), 256>>>(L, hT, LhT, NPAD, HCOLS, NPAD);
        k_gate<<<dim3(500, 2), 256>>>(W1, b1, t);
        sgemm<<<dim3(HCOLS / BN, NPAD / BM), 256>>>(L, rhT, LrhT, NPAD, HCOLS, NPAD);
        k_cand<<<500, 256>>>(W2, b2, t);
    }

    k_out<<<(BATCH * NNODE * HID + 255) / 256, 256>>>(out);
}

// round 4
// speedup vs baseline: 1.6924x; 1.6901x over previous
#include <cuda_runtime.h>
#include <cuda_bf16.h>
#include <math.h>
#include <stdint.h>

#define NNODE 1000
#define NPAD  1024
#define BATCH 32
#define SEQ   48
#define HID   64
#define FEATD 40
#define XCOLS (SEQ*BATCH*FEATD)   // 61440
#define HCOLS (BATCH*HID)         // 2048
#define KIN   104

typedef __nv_bfloat16 bf16;

// ---------------- static device scratch ----------------
__device__ float g_dis[NPAD];
__device__ __align__(128) bf16  g_Lhi[NPAD*NPAD];
__device__ __align__(128) bf16  g_Llo[NPAD*NPAD];
__device__ __align__(128) float g_xT  [(size_t)NPAD*XCOLS];   // [node][col]
__device__ __align__(128) bf16  g_xTrH[(size_t)XCOLS*NPAD];   // [col][node]
__device__ __align__(128) bf16  g_xTrL[(size_t)XCOLS*NPAD];
__device__ __align__(128) float g_LxT [(size_t)NPAD*XCOLS];   // fp32 [node][col]
__device__ __align__(128) float g_hT  [NPAD*HCOLS];
__device__ __align__(128) float g_rhT [NPAD*HCOLS];
__device__ __align__(128) float g_uT  [NPAD*HCOLS];
__device__ __align__(128) float g_LhT [NPAD*HCOLS];
__device__ __align__(128) float g_LrhT[NPAD*HCOLS];
__device__ __align__(128) bf16  g_hTrH[HCOLS*NPAD];
__device__ __align__(128) bf16  g_hTrL[HCOLS*NPAD];
__device__ __align__(128) bf16  g_rhTrH[HCOLS*NPAD];
__device__ __align__(128) bf16  g_rhTrL[HCOLS*NPAD];

__device__ __forceinline__ void split2(float v, bf16& h, bf16& l) {
    h = __float2bfloat16(v);
    l = __float2bfloat16(v - __bfloat162float(h));
}

// ---------------- prep ----------------
__global__ void k_zero_state() {
    int i = blockIdx.x * blockDim.x + threadIdx.x;
    if (i < NPAD * HCOLS) {
        g_hT[i] = 0.f;
        if (i >= NNODE * HCOLS) g_rhT[i] = 0.f;
    }
}
__global__ void k_zero_xpad() {
    size_t i = (size_t)blockIdx.x * blockDim.x + threadIdx.x;
    size_t tot = (size_t)(NPAD - NNODE) * XCOLS;
    if (i < tot) g_xT[(size_t)NNODE * XCOLS + i] = 0.f;
}
__global__ void k_rowsum(const float* __restrict__ adj) {
    int m = blockIdx.x, tid = threadIdx.x;
    float s = 0.f;
    for (int k = tid; k < NNODE; k += 256) s += adj[m * NNODE + k];
    __shared__ float sm[256];
    sm[tid] = s; __syncthreads();
    for (int st = 128; st > 0; st >>= 1) { if (tid < st) sm[tid] += sm[tid + st]; __syncthreads(); }
    if (tid == 0) g_dis[m] = rsqrtf(sm[0] + 1.0f);
}
__global__ void k_buildL(const float* __restrict__ adj) {
    int i = blockIdx.x * blockDim.x + threadIdx.x;
    if (i >= NPAD * NPAD) return;
    int m = i >> 10, n = i & (NPAD - 1);
    float v = 0.f;
    if (m < NNODE && n < NNODE)
        v = g_dis[m] * (adj[m * NNODE + n] + (m == n ? 1.f : 0.f)) * g_dis[n];
    bf16 h, l; split2(v, h, l);
    g_Lhi[i] = h; g_Llo[i] = l;
}
__global__ void k_aspect(const float* __restrict__ inp,
                         const float* __restrict__ Wo, const float* __restrict__ bo,
                         const float* __restrict__ Wd, const float* __restrict__ bd,
                         const float* __restrict__ We, const float* __restrict__ be,
                         const float* __restrict__ Wi, const float* __restrict__ bi) {
    size_t i = (size_t)blockIdx.x * blockDim.x + threadIdx.x;
    if (i >= (size_t)NNODE * XCOLS) return;
    int n = (int)(i / XCOLS);
    int col = (int)(i - (size_t)n * XCOLS);
    int s = col / (BATCH * FEATD);
    int rem = col - s * (BATCH * FEATD);
    int b = rem / FEATD, f = rem - b * FEATD;
    const float* base = inp + (((size_t)(b * SEQ + s) * NNODE + n) * 21);
    int fo = f % 10;
    float acc;
    if (f < 10) {
        const int idx[5] = {2, 5, 8, 9, 12};
        acc = __ldg(bo + fo);
        #pragma unroll
        for (int j = 0; j < 5; j++) acc += __ldg(base + idx[j]) * __ldg(Wo + j * 10 + fo);
    } else if (f < 20) {
        const int idx[3] = {10, 14, 15};
        acc = __ldg(bd + fo);
        #pragma unroll
        for (int j = 0; j < 3; j++) acc += __ldg(base + idx[j]) * __ldg(Wd + j * 10 + fo);
    } else if (f < 30) {
        const int idx[2] = {13, 17};
        acc = __ldg(be + fo);
        #pragma unroll
        for (int j = 0; j < 2; j++) acc += __ldg(base + idx[j]) * __ldg(We + j * 10 + fo);
    } else {
        const int idx[2] = {19, 20};
        acc = __ldg(bi + fo);
        #pragma unroll
        for (int j = 0; j < 2; j++) acc += __ldg(base + idx[j]) * __ldg(Wi + j * 10 + fo);
    }
    g_xT[(size_t)n * XCOLS + col] = acc;
}
// transpose + split: fp32 [1024][C] -> hi/lo bf16 [C][1024]
__global__ void k_tsplit(const float* __restrict__ in, bf16* __restrict__ oh,
                         bf16* __restrict__ ol, int C) {
    __shared__ float tile[32][33];
    int tx = threadIdx.x, ty = threadIdx.y;
    int c0 = blockIdx.x * 32, n0 = blockIdx.y * 32;
    tile[ty][tx] = in[(size_t)(n0 + ty) * C + c0 + tx];
    __syncthreads();
    float v = tile[tx][ty];
    bf16 h, l; split2(v, h, l);
    size_t o = (size_t)(c0 + ty) * NPAD + n0 + tx;
    oh[o] = h; ol[o] = l;
}

// ---------------- bf16x3 mma.sync GEMM: C[m][n] = sum_k A[m][k]*B[n][k] ----------------
// A = [M][1024] K-major, B = [N][1024] K-major, C fp32 [m][ldc]. K = NPAD fixed.
#define SApad 40
__device__ __forceinline__ void mma16816(float* d, const uint32_t* a, const uint32_t* b) {
    asm volatile(
        "mma.sync.aligned.m16n8k16.row.col.f32.bf16.bf16.f32 "
        "{%0,%1,%2,%3}, {%4,%5,%6,%7}, {%8,%9}, {%0,%1,%2,%3};"
        : "+f"(d[0]), "+f"(d[1]), "+f"(d[2]), "+f"(d[3])
        : "r"(a[0]), "r"(a[1]), "r"(a[2]), "r"(a[3]), "r"(b[0]), "r"(b[1]));
}
__global__ __launch_bounds__(256, 1)
void mma_gemm(const bf16* __restrict__ Ahi, const bf16* __restrict__ Alo,
              const bf16* __restrict__ Bhi, const bf16* __restrict__ Blo,
              float* __restrict__ C, int ldc) {
    __shared__ bf16 sAh[128 * SApad], sAl[128 * SApad];
    __shared__ bf16 sBh[128 * SApad], sBl[128 * SApad];
    int tid = threadIdx.x;
    int wid = tid >> 5, lane = tid & 31;
    int m0 = blockIdx.y * 128, n0 = blockIdx.x * 128;
    int wm = (wid & 1) * 64;   // warp row offset in tile
    int wn = (wid >> 1) * 32;  // warp col offset in tile
    int qr = lane >> 2;        // 0..7
    int qc = lane & 3;         // word index (element = qc*2)
    float acc[4][4][4];
    #pragma unroll
    for (int a = 0; a < 4; a++)
        #pragma unroll
        for (int b = 0; b < 4; b++)
            #pragma unroll
            for (int c = 0; c < 4; c++) acc[a][b][c] = 0.f;

    for (int k0 = 0; k0 < NPAD; k0 += 32) {
        // load 4 tiles of 128 rows x 32 bf16 each (one uint4 = 8 bf16)
        #pragma unroll
        for (int it = 0; it < 8; it++) {
            int i = it * 256 + tid;            // 0..2047
            int t = i >> 9;                    // tile 0..3
            int rest = i & 511;
            int r = rest >> 2, j = rest & 3;
            const bf16* src = (t == 0) ? Ahi : (t == 1) ? Alo : (t == 2) ? Bhi : Blo;
            int rowbase = (t < 2) ? m0 : n0;
            bf16* dst = (t == 0) ? sAh : (t == 1) ? sAl : (t == 2) ? sBh : sBl;
            uint4 v = *(const uint4*)(src + (size_t)(rowbase + r) * NPAD + k0 + j * 8);
            *(uint4*)(dst + r * SApad + j * 8) = v;
        }
        __syncthreads();
        #pragma unroll
        for (int ks = 0; ks < 32; ks += 16) {
            uint32_t ah[4][4], al[4][4], bh[4][2], bl[4][2];
            #pragma unroll
            for (int mi = 0; mi < 4; mi++) {
                int r = wm + mi * 16 + qr;
                ah[mi][0] = *(const uint32_t*)(sAh + r * SApad + ks + qc * 2);
                ah[mi][1] = *(const uint32_t*)(sAh + (r + 8) * SApad + ks + qc * 2);
                ah[mi][2] = *(const uint32_t*)(sAh + r * SApad + ks + 8 + qc * 2);
                ah[mi][3] = *(const uint32_t*)(sAh + (r + 8) * SApad + ks + 8 + qc * 2);
            }
            #pragma unroll
            for (int ni = 0; ni < 4; ni++) {
                int r = wn + ni * 8 + qr;
                bh[ni][0] = *(const uint32_t*)(sBh + r * SApad + ks + qc * 2);
                bh[ni][1] = *(const uint32_t*)(sBh + r * SApad + ks + 8 + qc * 2);
            }
            #pragma unroll
            for (int mi = 0; mi < 4; mi++)
                #pragma unroll
                for (int ni = 0; ni < 4; ni++) mma16816(acc[mi][ni], ah[mi], bh[ni]);
            #pragma unroll
            for (int mi = 0; mi < 4; mi++) {
                int r = wm + mi * 16 + qr;
                al[mi][0] = *(const uint32_t*)(sAl + r * SApad + ks + qc * 2);
                al[mi][1] = *(const uint32_t*)(sAl + (r + 8) * SApad + ks + qc * 2);
                al[mi][2] = *(const uint32_t*)(sAl + r * SApad + ks + 8 + qc * 2);
                al[mi][3] = *(const uint32_t*)(sAl + (r + 8) * SApad + ks + 8 + qc * 2);
            }
            #pragma unroll
            for (int mi = 0; mi < 4; mi++)
                #pragma unroll
                for (int ni = 0; ni < 4; ni++) mma16816(acc[mi][ni], al[mi], bh[ni]);
            #pragma unroll
            for (int ni = 0; ni < 4; ni++) {
                int r = wn + ni * 8 + qr;
                bl[ni][0] = *(const uint32_t*)(sBl + r * SApad + ks + qc * 2);
                bl[ni][1] = *(const uint32_t*)(sBl + r * SApad + ks + 8 + qc * 2);
            }
            #pragma unroll
            for (int mi = 0; mi < 4; mi++)
                #pragma unroll
                for (int ni = 0; ni < 4; ni++) mma16816(acc[mi][ni], ah[mi], bl[ni]);
        }
        __syncthreads();
    }
    // epilogue
    #pragma unroll
    for (int mi = 0; mi < 4; mi++) {
        int r = m0 + wm + mi * 16 + qr;
        #pragma unroll
        for (int ni = 0; ni < 4; ni++) {
            int cc = n0 + wn + ni * 8 + qc * 2;
            *(float2*)(C + (size_t)r * ldc + cc)       = make_float2(acc[mi][ni][0], acc[mi][ni][1]);
            *(float2*)(C + (size_t)(r + 8) * ldc + cc) = make_float2(acc[mi][ni][2], acc[mi][ni][3]);
        }
    }
}

// ---------------- gate / cand (identical to R1) ----------------
__global__ __launch_bounds__(256)
void k_gate(const float* __restrict__ W1, const float* __restrict__ b1, int t) {
    __shared__ float Ws[KIN * 64];
    __shared__ float bs[64];
    int half = blockIdx.y;
    for (int i = threadIdx.x; i < KIN * 64; i += 256)
        Ws[i] = W1[(i >> 6) * 128 + half * 64 + (i & 63)];
    if (threadIdx.x < 64) bs[threadIdx.x] = b1[half * 64 + threadIdx.x];
    __syncthreads();
    int lane = threadIdx.x & 31, warp = threadIdx.x >> 5;
    for (int r = 0; r < 8; ++r) {
        int row = (blockIdx.x * 8 + warp) + r * 4000;
        int n = row >> 5, b = row & 31;
        const float* lx = g_LxT + (size_t)n * XCOLS + t * (BATCH * FEATD) + b * FEATD;
        const float* lh = g_LhT + n * HCOLS + b * HID;
        float v0 = lx[lane];
        float v1 = (lane < 8) ? lx[32 + lane] : lh[lane - 8];
        float v2 = lh[24 + lane];
        float v3 = (lane < 8) ? lh[56 + lane] : 0.f;
        float a0 = bs[lane], a1 = bs[lane + 32];
        #pragma unroll
        for (int k = 0; k < KIN; ++k) {
            float src = (k < 32) ? v0 : (k < 64) ? v1 : (k < 96) ? v2 : v3;
            float val = __shfl_sync(0xffffffffu, src, k & 31);
            a0 += val * Ws[k * 64 + lane];
            a1 += val * Ws[k * 64 + lane + 32];
        }
        float s0 = 1.f / (1.f + expf(-a0));
        float s1 = 1.f / (1.f + expf(-a1));
        if (n < 500) {
            int o = (2 * n + half) * HCOLS + b * HID;
            g_rhT[o + lane]      = g_hT[o + lane]      * s0;
            g_rhT[o + lane + 32] = g_hT[o + lane + 32] * s1;
        } else {
            int o = (2 * (n - 500) + half) * HCOLS + b * HID;
            g_uT[o + lane]      = s0;
            g_uT[o + lane + 32] = s1;
        }
    }
}
__global__ __launch_bounds__(256)
void k_cand(const float* __restrict__ W2, const float* __restrict__ b2, int t) {
    __shared__ float Ws[KIN * 64];
    __shared__ float bs[64];
    for (int i = threadIdx.x; i < KIN * 64; i += 256) Ws[i] = W2[i];
    if (threadIdx.x < 64) bs[threadIdx.x] = b2[threadIdx.x];
    __syncthreads();
    int lane = threadIdx.x & 31, warp = threadIdx.x >> 5;
    for (int r = 0; r < 8; ++r) {
        int row = (blockIdx.x * 8 + warp) + r * 4000;
        int n = row >> 5, b = row & 31;
        const float* lx  = g_LxT  + (size_t)n * XCOLS + t * (BATCH * FEATD) + b * FEATD;
        const float* lrh = g_LrhT + n * HCOLS + b * HID;
        float v0 = lx[lane];
        float v1 = (lane < 8) ? lx[32 + lane] : lrh[lane - 8];
        float v2 = lrh[24 + lane];
        float v3 = (lane < 8) ? lrh[56 + lane] : 0.f;
        float a0 = bs[lane], a1 = bs[lane + 32];
        #pragma unroll
        for (int k = 0; k < KIN; ++k) {
            float src = (k < 32) ? v0 : (k < 64) ? v1 : (k < 96) ? v2 : v3;
            float val = __shfl_sync(0xffffffffu, src, k & 31);
            a0 += val * Ws[k * 64 + lane];
            a1 += val * Ws[k * 64 + lane + 32];
        }
        float c0 = tanhf(a0), c1 = tanhf(a1);
        int o = n * HCOLS + b * HID;
        float u0 = g_uT[o + lane], u1 = g_uT[o + lane + 32];
        float h0 = g_hT[o + lane], h1 = g_hT[o + lane + 32];
        g_hT[o + lane]      = u0 * h0 + (1.f - u0) * c0;
        g_hT[o + lane + 32] = u1 * h1 + (1.f - u1) * c1;
    }
}
__global__ void k_out(float* __restrict__ out) {
    int i = blockIdx.x * blockDim.x + threadIdx.x;
    if (i >= BATCH * NNODE * HID) return;
    int ch = i & (HID - 1);
    int n  = (i >> 6) % NNODE;
    int b  = i / (NNODE * HID);
    out[i] = g_hT[n * HCOLS + b * HID + ch];
}

// ---------------- launcher ----------------
extern "C" void kernel_launch(void* const* d_in, const int* in_sizes, int n_in,
                              void* d_out, int out_size) {
    const float* inp = (const float*)d_in[0];
    const float* adj = (const float*)d_in[1];
    const float* Wo = (const float*)d_in[2];  const float* bo = (const float*)d_in[3];
    const float* Wd = (const float*)d_in[4];  const float* bd = (const float*)d_in[5];
    const float* We = (const float*)d_in[6];  const float* be = (const float*)d_in[7];
    const float* Wi = (const float*)d_in[8];  const float* bi = (const float*)d_in[9];
    const float* W1 = (const float*)d_in[10]; const float* b1 = (const float*)d_in[11];
    const float* W2 = (const float*)d_in[12]; const float* b2 = (const float*)d_in[13];
    float* out = (float*)d_out;

    bf16 *Lhi, *Llo, *xTrH, *xTrL, *hTrH, *hTrL, *rhTrH, *rhTrL;
    float *xT, *LxT, *hT, *rhT, *LhT, *LrhT;
    cudaGetSymbolAddress((void**)&Lhi, g_Lhi);   cudaGetSymbolAddress((void**)&Llo, g_Llo);
    cudaGetSymbolAddress((void**)&xT, g_xT);     cudaGetSymbolAddress((void**)&LxT, g_LxT);
    cudaGetSymbolAddress((void**)&xTrH, g_xTrH); cudaGetSymbolAddress((void**)&xTrL, g_xTrL);
    cudaGetSymbolAddress((void**)&hT, g_hT);     cudaGetSymbolAddress((void**)&rhT, g_rhT);
    cudaGetSymbolAddress((void**)&hTrH, g_hTrH); cudaGetSymbolAddress((void**)&hTrL, g_hTrL);
    cudaGetSymbolAddress((void**)&rhTrH, g_rhTrH); cudaGetSymbolAddress((void**)&rhTrL, g_rhTrL);
    cudaGetSymbolAddress((void**)&LhT, g_LhT);   cudaGetSymbolAddress((void**)&LrhT, g_LrhT);

    k_zero_state<<<(NPAD * HCOLS + 255) / 256, 256>>>();
    k_zero_xpad<<<(int)(((size_t)(NPAD - NNODE) * XCOLS + 255) / 256), 256>>>();
    k_rowsum<<<NNODE, 256>>>(adj);
    k_buildL<<<(NPAD * NPAD) / 256, 256>>>(adj);
    k_aspect<<<(int)(((size_t)NNODE * XCOLS + 255) / 256), 256>>>(inp, Wo, bo, Wd, bd, We, be, Wi, bi);

    // x: transpose+split, then hoisted LxT = L @ x  (tensor cores)
    k_tsplit<<<dim3(XCOLS / 32, 32), dim3(32, 32)>>>(xT, xTrH, xTrL, XCOLS);
    mma_gemm<<<dim3(XCOLS / 128, NPAD / 128), 256>>>(Lhi, Llo, xTrH, xTrL, LxT, XCOLS);

    for (int t = 0; t < SEQ; ++t) {
        k_tsplit<<<dim3(HCOLS / 32, 32), dim3(32, 32)>>>(hT, hTrH, hTrL, HCOLS);
        mma_gemm<<<dim3(HCOLS / 128, NPAD / 128), 256>>>(Lhi, Llo, hTrH, hTrL, LhT, HCOLS);
        k_gate<<<dim3(500, 2), 256>>>(W1, b1, t);
        k_tsplit<<<dim3(HCOLS / 32, 32), dim3(32, 32)>>>(rhT, rhTrH, rhTrL, HCOLS);
        mma_gemm<<<dim3(HCOLS / 128, NPAD / 128), 256>>>(Lhi, Llo, rhTrH, rhTrL, LrhT, HCOLS);
        k_cand<<<500, 256>>>(W2, b2, t);
    }

    k_out<<<(BATCH * NNODE * HID + 255) / 256, 256>>>(out);
}

// round 5
// speedup vs baseline: 2.5614x; 1.5134x over previous
#include <cuda_runtime.h>
#include <cuda_bf16.h>
#include <math.h>
#include <stdint.h>

#define NNODE 1000
#define NPAD  1024
#define BATCH 32
#define SEQ   48
#define HID   64
#define FEATD 40
#define XCOLS (SEQ*BATCH*FEATD)   // 61440
#define HCOLS (BATCH*HID)         // 2048
#define GP    120                 // padded K row for gate/cand smem tiles

typedef __nv_bfloat16 bf16;

// ---------------- static device scratch ----------------
__device__ float g_dis[NPAD];
__device__ __align__(128) bf16  g_Lhi[NPAD*NPAD];
__device__ __align__(128) bf16  g_Llo[NPAD*NPAD];
__device__ __align__(128) float g_xT  [(size_t)NPAD*XCOLS];   // [node][col]
__device__ __align__(128) float g_LxT [(size_t)NPAD*XCOLS];   // [node][col]
__device__ __align__(128) float g_hT  [NPAD*HCOLS];
__device__ __align__(128) float g_rhT [NPAD*HCOLS];
__device__ __align__(128) float g_uT  [NPAD*HCOLS];
__device__ __align__(128) float g_LhT [NPAD*HCOLS];
__device__ __align__(128) float g_LrhT[NPAD*HCOLS];

__device__ __forceinline__ void split2(float v, bf16& h, bf16& l) {
    h = __float2bfloat16(v);
    l = __float2bfloat16(v - __bfloat162float(h));
}
__device__ __forceinline__ uint32_t packhl(bf16 a, bf16 b) {
    __nv_bfloat162 t = __halves2bfloat162(a, b);
    return *reinterpret_cast<uint32_t*>(&t);
}

// ---------------- prep ----------------
__global__ void k_zero_state() {
    int i = blockIdx.x * blockDim.x + threadIdx.x;
    if (i < NPAD * HCOLS) {
        g_hT[i] = 0.f;
        if (i >= NNODE * HCOLS) g_rhT[i] = 0.f;
    }
}
__global__ void k_zero_xpad() {
    size_t i = (size_t)blockIdx.x * blockDim.x + threadIdx.x;
    size_t tot = (size_t)(NPAD - NNODE) * XCOLS;
    if (i < tot) g_xT[(size_t)NNODE * XCOLS + i] = 0.f;
}
__global__ void k_rowsum(const float* __restrict__ adj) {
    int m = blockIdx.x, tid = threadIdx.x;
    float s = 0.f;
    for (int k = tid; k < NNODE; k += 256) s += adj[m * NNODE + k];
    __shared__ float sm[256];
    sm[tid] = s; __syncthreads();
    for (int st = 128; st > 0; st >>= 1) { if (tid < st) sm[tid] += sm[tid + st]; __syncthreads(); }
    if (tid == 0) g_dis[m] = rsqrtf(sm[0] + 1.0f);
}
__global__ void k_buildL(const float* __restrict__ adj) {
    int i = blockIdx.x * blockDim.x + threadIdx.x;
    if (i >= NPAD * NPAD) return;
    int m = i >> 10, n = i & (NPAD - 1);
    float v = 0.f;
    if (m < NNODE && n < NNODE)
        v = g_dis[m] * (adj[m * NNODE + n] + (m == n ? 1.f : 0.f)) * g_dis[n];
    bf16 h, l; split2(v, h, l);
    g_Lhi[i] = h; g_Llo[i] = l;
}
__global__ void k_aspect(const float* __restrict__ inp,
                         const float* __restrict__ Wo, const float* __restrict__ bo,
                         const float* __restrict__ Wd, const float* __restrict__ bd,
                         const float* __restrict__ We, const float* __restrict__ be,
                         const float* __restrict__ Wi, const float* __restrict__ bi) {
    size_t i = (size_t)blockIdx.x * blockDim.x + threadIdx.x;
    if (i >= (size_t)NNODE * XCOLS) return;
    int n = (int)(i / XCOLS);
    int col = (int)(i - (size_t)n * XCOLS);
    int s = col / (BATCH * FEATD);
    int rem = col - s * (BATCH * FEATD);
    int b = rem / FEATD, f = rem - b * FEATD;
    const float* base = inp + (((size_t)(b * SEQ + s) * NNODE + n) * 21);
    int fo = f % 10;
    float acc;
    if (f < 10) {
        const int idx[5] = {2, 5, 8, 9, 12};
        acc = __ldg(bo + fo);
        #pragma unroll
        for (int j = 0; j < 5; j++) acc += __ldg(base + idx[j]) * __ldg(Wo + j * 10 + fo);
    } else if (f < 20) {
        const int idx[3] = {10, 14, 15};
        acc = __ldg(bd + fo);
        #pragma unroll
        for (int j = 0; j < 3; j++) acc += __ldg(base + idx[j]) * __ldg(Wd + j * 10 + fo);
    } else if (f < 30) {
        const int idx[2] = {13, 17};
        acc = __ldg(be + fo);
        #pragma unroll
        for (int j = 0; j < 2; j++) acc += __ldg(base + idx[j]) * __ldg(We + j * 10 + fo);
    } else {
        const int idx[2] = {19, 20};
        acc = __ldg(bi + fo);
        #pragma unroll
        for (int j = 0; j < 2; j++) acc += __ldg(base + idx[j]) * __ldg(Wi + j * 10 + fo);
    }
    g_xT[(size_t)n * XCOLS + col] = acc;
}

// ---------------- mma16816 ----------------
__device__ __forceinline__ void mma16816(float* d, const uint32_t* a, const uint32_t* b) {
    asm volatile(
        "mma.sync.aligned.m16n8k16.row.col.f32.bf16.bf16.f32 "
        "{%0,%1,%2,%3}, {%4,%5,%6,%7}, {%8,%9}, {%0,%1,%2,%3};"
        : "+f"(d[0]), "+f"(d[1]), "+f"(d[2]), "+f"(d[3])
        : "r"(a[0]), "r"(a[1]), "r"(a[2]), "r"(a[3]), "r"(b[0]), "r"(b[1]));
}

// ---------------- GEMM: C[m][n] = sum_k A[m][k]*B[k][n]; A bf16 hi/lo K-major; B fp32 row-major ----------------
// B split + transposed into smem on the fly. Register-prefetch pipeline over 32 K-chunks.
__global__ __launch_bounds__(256, 1)
void mma_gemm2(const bf16* __restrict__ Ahi, const bf16* __restrict__ Alo,
               const float* __restrict__ B, float* __restrict__ C, int ldc) {
    __shared__ bf16 sAh[128 * 40], sAl[128 * 40], sBh[128 * 40], sBl[128 * 40];
    int tid = threadIdx.x, wid = tid >> 5, lane = tid & 31;
    int m0 = blockIdx.y * 128, n0 = blockIdx.x * 128;
    int wm = (wid & 1) * 64, wn = (wid >> 1) * 32;
    int qr = lane >> 2, qc = lane & 3;
    int bn = tid & 127, bk4 = (tid >> 7) * 16;
    const float* Bp = B + n0 + bn;
    float acc[4][4][4];
    #pragma unroll
    for (int a = 0; a < 4; a++)
        #pragma unroll
        for (int b = 0; b < 4; b++)
            #pragma unroll
            for (int c = 0; c < 4; c++) acc[a][b][c] = 0.f;

    uint4 pa[4];
    float pb[16];
    // prologue: prefetch chunk 0
    #pragma unroll
    for (int it = 0; it < 4; it++) {
        int i = it * 256 + tid, t = i >> 9, r = (i & 511) >> 2, j = i & 3;
        const bf16* s = t ? Alo : Ahi;
        pa[it] = *(const uint4*)(s + (size_t)(m0 + r) * NPAD + j * 8);
    }
    #pragma unroll
    for (int j = 0; j < 16; j++) pb[j] = Bp[(size_t)(bk4 + j) * ldc];

    for (int c = 0; c < 32; c++) {
        // commit prefetched chunk to smem
        #pragma unroll
        for (int it = 0; it < 4; it++) {
            int i = it * 256 + tid, t = i >> 9, r = (i & 511) >> 2, j = i & 3;
            bf16* d = t ? sAl : sAh;
            *(uint4*)(d + r * 40 + j * 8) = pa[it];
        }
        {
            uint32_t hw[8], lw[8];
            #pragma unroll
            for (int j = 0; j < 8; j++) {
                bf16 h0, l0, h1, l1;
                split2(pb[2 * j], h0, l0);
                split2(pb[2 * j + 1], h1, l1);
                hw[j] = packhl(h0, h1);
                lw[j] = packhl(l0, l1);
            }
            *(uint4*)(sBh + bn * 40 + bk4)     = make_uint4(hw[0], hw[1], hw[2], hw[3]);
            *(uint4*)(sBh + bn * 40 + bk4 + 8) = make_uint4(hw[4], hw[5], hw[6], hw[7]);
            *(uint4*)(sBl + bn * 40 + bk4)     = make_uint4(lw[0], lw[1], lw[2], lw[3]);
            *(uint4*)(sBl + bn * 40 + bk4 + 8) = make_uint4(lw[4], lw[5], lw[6], lw[7]);
        }
        __syncthreads();
        if (c < 31) {  // prefetch next chunk (overlaps with compute below)
            int k0 = (c + 1) * 32;
            #pragma unroll
            for (int it = 0; it < 4; it++) {
                int i = it * 256 + tid, t = i >> 9, r = (i & 511) >> 2, j = i & 3;
                const bf16* s = t ? Alo : Ahi;
                pa[it] = *(const uint4*)(s + (size_t)(m0 + r) * NPAD + k0 + j * 8);
            }
            #pragma unroll
            for (int j = 0; j < 16; j++) pb[j] = Bp[(size_t)(k0 + bk4 + j) * ldc];
        }
        #pragma unroll
        for (int ks = 0; ks < 32; ks += 16) {
            uint32_t ah[4][4], al[4][4], bh[4][2], bl[4][2];
            #pragma unroll
            for (int mi = 0; mi < 4; mi++) {
                int r = wm + mi * 16 + qr;
                ah[mi][0] = *(const uint32_t*)(sAh + r * 40 + ks + qc * 2);
                ah[mi][1] = *(const uint32_t*)(sAh + (r + 8) * 40 + ks + qc * 2);
                ah[mi][2] = *(const uint32_t*)(sAh + r * 40 + ks + 8 + qc * 2);
                ah[mi][3] = *(const uint32_t*)(sAh + (r + 8) * 40 + ks + 8 + qc * 2);
            }
            #pragma unroll
            for (int ni = 0; ni < 4; ni++) {
                int r = wn + ni * 8 + qr;
                bh[ni][0] = *(const uint32_t*)(sBh + r * 40 + ks + qc * 2);
                bh[ni][1] = *(const uint32_t*)(sBh + r * 40 + ks + 8 + qc * 2);
            }
            #pragma unroll
            for (int mi = 0; mi < 4; mi++)
                #pragma unroll
                for (int ni = 0; ni < 4; ni++) mma16816(acc[mi][ni], ah[mi], bh[ni]);
            #pragma unroll
            for (int mi = 0; mi < 4; mi++) {
                int r = wm + mi * 16 + qr;
                al[mi][0] = *(const uint32_t*)(sAl + r * 40 + ks + qc * 2);
                al[mi][1] = *(const uint32_t*)(sAl + (r + 8) * 40 + ks + qc * 2);
                al[mi][2] = *(const uint32_t*)(sAl + r * 40 + ks + 8 + qc * 2);
                al[mi][3] = *(const uint32_t*)(sAl + (r + 8) * 40 + ks + 8 + qc * 2);
            }
            #pragma unroll
            for (int mi = 0; mi < 4; mi++)
                #pragma unroll
                for (int ni = 0; ni < 4; ni++) mma16816(acc[mi][ni], al[mi], bh[ni]);
            #pragma unroll
            for (int ni = 0; ni < 4; ni++) {
                int r = wn + ni * 8 + qr;
                bl[ni][0] = *(const uint32_t*)(sBl + r * 40 + ks + qc * 2);
                bl[ni][1] = *(const uint32_t*)(sBl + r * 40 + ks + 8 + qc * 2);
            }
            #pragma unroll
            for (int mi = 0; mi < 4; mi++)
                #pragma unroll
                for (int ni = 0; ni < 4; ni++) mma16816(acc[mi][ni], ah[mi], bl[ni]);
        }
        __syncthreads();
    }
    #pragma unroll
    for (int mi = 0; mi < 4; mi++) {
        int r = m0 + wm + mi * 16 + qr;
        #pragma unroll
        for (int ni = 0; ni < 4; ni++) {
            int cc = n0 + wn + ni * 8 + qc * 2;
            *(float2*)(C + (size_t)r * ldc + cc)       = make_float2(acc[mi][ni][0], acc[mi][ni][1]);
            *(float2*)(C + (size_t)(r + 8) * ldc + cc) = make_float2(acc[mi][ni][2], acc[mi][ni][3]);
        }
    }
}

// ---------------- gate GEMM: rows (n*32+b), K=104 [Lx|Lh], N=128; fused sigmoid + chunk remap ----------------
__global__ __launch_bounds__(256, 1)
void k_gateG(const float* __restrict__ W1, const float* __restrict__ b1, int t) {
    extern __shared__ char dyn[];
    bf16* sAh = (bf16*)dyn;
    bf16* sAl = sAh + 128 * GP;
    bf16* sWh = sAl + 128 * GP;
    bf16* sWl = sWh + 128 * GP;
    float* sb = (float*)(sWl + 128 * GP);
    int tid = threadIdx.x, wid = tid >> 5, lane = tid & 31;
    int n0 = blockIdx.x * 4;
    bf16 z = __float2bfloat16(0.f);
    for (int g = tid; g < 128 * 8; g += 256) {
        int r = g >> 3, k = 104 + (g & 7);
        sAh[r * GP + k] = z; sAl[r * GP + k] = z;
        sWh[r * GP + k] = z; sWl[r * GP + k] = z;
    }
    for (int g = tid; g < 4 * 1280; g += 256) {
        int ni = g / 1280, rem = g - ni * 1280;
        float v = g_LxT[(size_t)(n0 + ni) * XCOLS + (size_t)t * 1280 + rem];
        int b = rem / 40, k = rem - b * 40;
        int row = ni * 32 + b;
        bf16 h, l; split2(v, h, l);
        sAh[row * GP + k] = h; sAl[row * GP + k] = l;
    }
    for (int g = tid; g < 4 * 2048; g += 256) {
        int ni = g >> 11, rem = g & 2047;
        float v = g_LhT[(n0 + ni) * HCOLS + rem];
        int row = ni * 32 + (rem >> 6), k = 40 + (rem & 63);
        bf16 h, l; split2(v, h, l);
        sAh[row * GP + k] = h; sAl[row * GP + k] = l;
    }
    for (int g = tid; g < 104 * 128; g += 256) {
        int k = g >> 7, o = g & 127;
        bf16 h, l; split2(W1[g], h, l);
        sWh[o * GP + k] = h; sWl[o * GP + k] = l;
    }
    if (tid < 128) sb[tid] = b1[tid];
    __syncthreads();

    int wm = (wid & 1) * 64, wn = (wid >> 1) * 32;
    int qr = lane >> 2, qc = lane & 3;
    float acc[4][4][4];
    #pragma unroll
    for (int a = 0; a < 4; a++)
        #pragma unroll
        for (int b = 0; b < 4; b++)
            #pragma unroll
            for (int c = 0; c < 4; c++) acc[a][b][c] = 0.f;
    for (int ks = 0; ks < 112; ks += 16) {
        uint32_t ah[4][4], al[4][4], bh[4][2], bl[4][2];
        #pragma unroll
        for (int mi = 0; mi < 4; mi++) {
            int r = wm + mi * 16 + qr;
            ah[mi][0] = *(const uint32_t*)(sAh + r * GP + ks + qc * 2);
            ah[mi][1] = *(const uint32_t*)(sAh + (r + 8) * GP + ks + qc * 2);
            ah[mi][2] = *(const uint32_t*)(sAh + r * GP + ks + 8 + qc * 2);
            ah[mi][3] = *(const uint32_t*)(sAh + (r + 8) * GP + ks + 8 + qc * 2);
            al[mi][0] = *(const uint32_t*)(sAl + r * GP + ks + qc * 2);
            al[mi][1] = *(const uint32_t*)(sAl + (r + 8) * GP + ks + qc * 2);
            al[mi][2] = *(const uint32_t*)(sAl + r * GP + ks + 8 + qc * 2);
            al[mi][3] = *(const uint32_t*)(sAl + (r + 8) * GP + ks + 8 + qc * 2);
        }
        #pragma unroll
        for (int ni = 0; ni < 4; ni++) {
            int r = wn + ni * 8 + qr;
            bh[ni][0] = *(const uint32_t*)(sWh + r * GP + ks + qc * 2);
            bh[ni][1] = *(const uint32_t*)(sWh + r * GP + ks + 8 + qc * 2);
            bl[ni][0] = *(const uint32_t*)(sWl + r * GP + ks + qc * 2);
            bl[ni][1] = *(const uint32_t*)(sWl + r * GP + ks + 8 + qc * 2);
        }
        #pragma unroll
        for (int mi = 0; mi < 4; mi++)
            #pragma unroll
            for (int ni = 0; ni < 4; ni++) {
                mma16816(acc[mi][ni], ah[mi], bh[ni]);
                mma16816(acc[mi][ni], al[mi], bh[ni]);
                mma16816(acc[mi][ni], ah[mi], bl[ni]);
            }
    }
    #pragma unroll
    for (int mi = 0; mi < 4; mi++) {
        #pragma unroll
        for (int ni = 0; ni < 4; ni++) {
            int o = wn + ni * 8 + qc * 2;
            int half = o >> 6, ch = o & 63;
            #pragma unroll
            for (int hr = 0; hr < 2; hr++) {
                int row = wm + mi * 16 + qr + hr * 8;
                int n = n0 + (row >> 5), b = row & 31;
                float s0 = 1.f / (1.f + expf(-(acc[mi][ni][hr * 2]     + sb[o])));
                float s1 = 1.f / (1.f + expf(-(acc[mi][ni][hr * 2 + 1] + sb[o + 1])));
                if (n < 500) {
                    int idx = (2 * n + half) * HCOLS + b * 64 + ch;
                    float2 h2 = *(float2*)(g_hT + idx);
                    *(float2*)(g_rhT + idx) = make_float2(h2.x * s0, h2.y * s1);
                } else {
                    int idx = (2 * (n - 500) + half) * HCOLS + b * 64 + ch;
                    *(float2*)(g_uT + idx) = make_float2(s0, s1);
                }
            }
        }
    }
}

// ---------------- cand GEMM: K=104 [Lx|Lrh], N=64; fused tanh + GRU update ----------------
__global__ __launch_bounds__(256, 1)
void k_candG(const float* __restrict__ W2, const float* __restrict__ b2, int t) {
    extern __shared__ char dyn[];
    bf16* sAh = (bf16*)dyn;
    bf16* sAl = sAh + 128 * GP;
    bf16* sWh = sAl + 128 * GP;
    bf16* sWl = sWh + 64 * GP;
    float* sb = (float*)(sWl + 64 * GP);
    int tid = threadIdx.x, wid = tid >> 5, lane = tid & 31;
    int n0 = blockIdx.x * 4;
    bf16 z = __float2bfloat16(0.f);
    for (int g = tid; g < 128 * 8; g += 256) {
        int r = g >> 3, k = 104 + (g & 7);
        sAh[r * GP + k] = z; sAl[r * GP + k] = z;
        if (r < 64) { sWh[r * GP + k] = z; sWl[r * GP + k] = z; }
    }
    for (int g = tid; g < 4 * 1280; g += 256) {
        int ni = g / 1280, rem = g - ni * 1280;
        float v = g_LxT[(size_t)(n0 + ni) * XCOLS + (size_t)t * 1280 + rem];
        int b = rem / 40, k = rem - b * 40;
        int row = ni * 32 + b;
        bf16 h, l; split2(v, h, l);
        sAh[row * GP + k] = h; sAl[row * GP + k] = l;
    }
    for (int g = tid; g < 4 * 2048; g += 256) {
        int ni = g >> 11, rem = g & 2047;
        float v = g_LrhT[(n0 + ni) * HCOLS + rem];
        int row = ni * 32 + (rem >> 6), k = 40 + (rem & 63);
        bf16 h, l; split2(v, h, l);
        sAh[row * GP + k] = h; sAl[row * GP + k] = l;
    }
    for (int g = tid; g < 104 * 64; g += 256) {
        int k = g >> 6, o = g & 63;
        bf16 h, l; split2(W2[g], h, l);
        sWh[o * GP + k] = h; sWl[o * GP + k] = l;
    }
    if (tid < 64) sb[tid] = b2[tid];
    __syncthreads();

    int wm = (wid & 3) * 32, wn = (wid >> 2) * 32;
    int qr = lane >> 2, qc = lane & 3;
    float acc[2][4][4];
    #pragma unroll
    for (int a = 0; a < 2; a++)
        #pragma unroll
        for (int b = 0; b < 4; b++)
            #pragma unroll
            for (int c = 0; c < 4; c++) acc[a][b][c] = 0.f;
    for (int ks = 0; ks < 112; ks += 16) {
        uint32_t ah[2][4], al[2][4], bh[4][2], bl[4][2];
        #pragma unroll
        for (int mi = 0; mi < 2; mi++) {
            int r = wm + mi * 16 + qr;
            ah[mi][0] = *(const uint32_t*)(sAh + r * GP + ks + qc * 2);
            ah[mi][1] = *(const uint32_t*)(sAh + (r + 8) * GP + ks + qc * 2);
            ah[mi][2] = *(const uint32_t*)(sAh + r * GP + ks + 8 + qc * 2);
            ah[mi][3] = *(const uint32_t*)(sAh + (r + 8) * GP + ks + 8 + qc * 2);
            al[mi][0] = *(const uint32_t*)(sAl + r * GP + ks + qc * 2);
            al[mi][1] = *(const uint32_t*)(sAl + (r + 8) * GP + ks + qc * 2);
            al[mi][2] = *(const uint32_t*)(sAl + r * GP + ks + 8 + qc * 2);
            al[mi][3] = *(const uint32_t*)(sAl + (r + 8) * GP + ks + 8 + qc * 2);
        }
        #pragma unroll
        for (int ni = 0; ni < 4; ni++) {
            int r = wn + ni * 8 + qr;
            bh[ni][0] = *(const uint32_t*)(sWh + r * GP + ks + qc * 2);
            bh[ni][1] = *(const uint32_t*)(sWh + r * GP + ks + 8 + qc * 2);
            bl[ni][0] = *(const uint32_t*)(sWl + r * GP + ks + qc * 2);
            bl[ni][1] = *(const uint32_t*)(sWl + r * GP + ks + 8 + qc * 2);
        }
        #pragma unroll
        for (int mi = 0; mi < 2; mi++)
            #pragma unroll
            for (int ni = 0; ni < 4; ni++) {
                mma16816(acc[mi][ni], ah[mi], bh[ni]);
                mma16816(acc[mi][ni], al[mi], bh[ni]);
                mma16816(acc[mi][ni], ah[mi], bl[ni]);
            }
    }
    #pragma unroll
    for (int mi = 0; mi < 2; mi++) {
        #pragma unroll
        for (int ni = 0; ni < 4; ni++) {
            int o = wn + ni * 8 + qc * 2;
            #pragma unroll
            for (int hr = 0; hr < 2; hr++) {
                int row = wm + mi * 16 + qr + hr * 8;
                int n = n0 + (row >> 5), b = row & 31;
                float c0 = tanhf(acc[mi][ni][hr * 2]     + sb[o]);
                float c1 = tanhf(acc[mi][ni][hr * 2 + 1] + sb[o + 1]);
                int idx = n * HCOLS + b * 64 + o;
                float2 u2 = *(float2*)(g_uT + idx);
                float2 h2 = *(float2*)(g_hT + idx);
                *(float2*)(g_hT + idx) =
                    make_float2(u2.x * h2.x + (1.f - u2.x) * c0,
                                u2.y * h2.y + (1.f - u2.y) * c1);
            }
        }
    }
}

__global__ void k_out(float* __restrict__ out) {
    int i = blockIdx.x * blockDim.x + threadIdx.x;
    if (i >= BATCH * NNODE * HID) return;
    int ch = i & (HID - 1);
    int n  = (i >> 6) % NNODE;
    int b  = i / (NNODE * HID);
    out[i] = g_hT[n * HCOLS + b * HID + ch];
}

// ---------------- launcher ----------------
extern "C" void kernel_launch(void* const* d_in, const int* in_sizes, int n_in,
                              void* d_out, int out_size) {
    const float* inp = (const float*)d_in[0];
    const float* adj = (const float*)d_in[1];
    const float* Wo = (const float*)d_in[2];  const float* bo = (const float*)d_in[3];
    const float* Wd = (const float*)d_in[4];  const float* bd = (const float*)d_in[5];
    const float* We = (const float*)d_in[6];  const float* be = (const float*)d_in[7];
    const float* Wi = (const float*)d_in[8];  const float* bi = (const float*)d_in[9];
    const float* W1 = (const float*)d_in[10]; const float* b1 = (const float*)d_in[11];
    const float* W2 = (const float*)d_in[12]; const float* b2 = (const float*)d_in[13];
    float* out = (float*)d_out;

    const int GATE_SMEM = 4 * 128 * GP * 2 + 128 * 4;             // 123392
    const int CAND_SMEM = (2 * 128 + 2 * 64) * GP * 2 + 64 * 4;   // 92416
    cudaFuncSetAttribute(k_gateG, cudaFuncAttributeMaxDynamicSharedMemorySize, GATE_SMEM);
    cudaFuncSetAttribute(k_candG, cudaFuncAttributeMaxDynamicSharedMemorySize, CAND_SMEM);

    bf16 *Lhi, *Llo;
    float *xT, *LxT, *hT, *rhT, *LhT, *LrhT;
    cudaGetSymbolAddress((void**)&Lhi, g_Lhi);  cudaGetSymbolAddress((void**)&Llo, g_Llo);
    cudaGetSymbolAddress((void**)&xT, g_xT);    cudaGetSymbolAddress((void**)&LxT, g_LxT);
    cudaGetSymbolAddress((void**)&hT, g_hT);    cudaGetSymbolAddress((void**)&rhT, g_rhT);
    cudaGetSymbolAddress((void**)&LhT, g_LhT);  cudaGetSymbolAddress((void**)&LrhT, g_LrhT);

    k_zero_state<<<(NPAD * HCOLS + 255) / 256, 256>>>();
    k_zero_xpad<<<(int)(((size_t)(NPAD - NNODE) * XCOLS + 255) / 256), 256>>>();
    k_rowsum<<<NNODE, 256>>>(adj);
    k_buildL<<<(NPAD * NPAD) / 256, 256>>>(adj);
    k_aspect<<<(int)(((size_t)NNODE * XCOLS + 255) / 256), 256>>>(inp, Wo, bo, Wd, bd, We, be, Wi, bi);

    // hoisted LxT = L @ x (B = fp32 x, split+transposed in-kernel)
    mma_gemm2<<<dim3(XCOLS / 128, NPAD / 128), 256>>>(Lhi, Llo, xT, LxT, XCOLS);

    for (int t = 0; t < SEQ; ++t) {
        mma_gemm2<<<dim3(HCOLS / 128, NPAD / 128), 256>>>(Lhi, Llo, hT, LhT, HCOLS);
        k_gateG<<<250, 256, GATE_SMEM>>>(W1, b1, t);
        mma_gemm2<<<dim3(HCOLS / 128, NPAD / 128), 256>>>(Lhi, Llo, rhT, LrhT, HCOLS);
        k_candG<<<250, 256, CAND_SMEM>>>(W2, b2, t);
    }

    k_out<<<(BATCH * NNODE * HID + 255) / 256, 256>>>(out);
}

// round 7
// speedup vs baseline: 2.7069x; 1.0568x over previous
#include <cuda_runtime.h>
#include <cuda_bf16.h>
#include <math.h>
#include <stdint.h>

#define NNODE 1000
#define NPAD  1024
#define BATCH 32
#define SEQ   48
#define HID   64
#define FEATD 40
#define XCOLS (SEQ*BATCH*FEATD)   // 61440
#define HCOLS (BATCH*HID)         // 2048
#define GP    120

typedef __nv_bfloat16 bf16;

// ---------------- static device scratch ----------------
__device__ float g_dis[NPAD];
__device__ __align__(128) bf16  g_Lhi[NPAD*NPAD];
__device__ __align__(128) bf16  g_Llo[NPAD*NPAD];
__device__ __align__(128) float g_xT  [(size_t)NPAD*XCOLS];
__device__ __align__(128) float g_LxT [(size_t)NPAD*XCOLS];
__device__ __align__(128) float g_hT  [NPAD*HCOLS];
__device__ __align__(128) float g_rhT [NPAD*HCOLS];
__device__ __align__(128) float g_uT  [NPAD*HCOLS];
__device__ __align__(128) float g_LhT [NPAD*HCOLS];
__device__ __align__(128) float g_LrhT[NPAD*HCOLS];
__device__ __align__(128) bf16  g_W1h[128*112];   // zero-init covers k=104..111 pad
__device__ __align__(128) bf16  g_W1l[128*112];
__device__ __align__(128) bf16  g_W2h[64*112];
__device__ __align__(128) bf16  g_W2l[64*112];

__device__ __forceinline__ void split2(float v, bf16& h, bf16& l) {
    h = __float2bfloat16(v);
    l = __float2bfloat16(v - __bfloat162float(h));
}
__device__ __forceinline__ uint32_t packhl(bf16 a, bf16 b) {
    __nv_bfloat162 t = __halves2bfloat162(a, b);
    return *reinterpret_cast<uint32_t*>(&t);
}
__device__ __forceinline__ uint32_t smem_u32(const void* p) {
    uint32_t a;
    asm("{ .reg .u64 t; cvta.to.shared.u64 t, %1; cvt.u32.u64 %0, t; }" : "=r"(a) : "l"(p));
    return a;
}

// ---------------- prep ----------------
__global__ void k_zero_state() {
    int i = blockIdx.x * blockDim.x + threadIdx.x;
    if (i < NPAD * HCOLS) {
        g_hT[i] = 0.f;
        if (i >= NNODE * HCOLS) g_rhT[i] = 0.f;
    }
}
__global__ void k_zero_xpad() {
    size_t i = (size_t)blockIdx.x * blockDim.x + threadIdx.x;
    size_t tot = (size_t)(NPAD - NNODE) * XCOLS;
    if (i < tot) g_xT[(size_t)NNODE * XCOLS + i] = 0.f;
}
__global__ void k_rowsum(const float* __restrict__ adj) {
    int m = blockIdx.x, tid = threadIdx.x;
    float s = 0.f;
    for (int k = tid; k < NNODE; k += 256) s += adj[m * NNODE + k];
    __shared__ float sm[256];
    sm[tid] = s; __syncthreads();
    for (int st = 128; st > 0; st >>= 1) { if (tid < st) sm[tid] += sm[tid + st]; __syncthreads(); }
    if (tid == 0) g_dis[m] = rsqrtf(sm[0] + 1.0f);
}
__global__ void k_buildL(const float* __restrict__ adj) {
    int i = blockIdx.x * blockDim.x + threadIdx.x;
    if (i >= NPAD * NPAD) return;
    int m = i >> 10, n = i & (NPAD - 1);
    float v = 0.f;
    if (m < NNODE && n < NNODE)
        v = g_dis[m] * (adj[m * NNODE + n] + (m == n ? 1.f : 0.f)) * g_dis[n];
    bf16 h, l; split2(v, h, l);
    g_Lhi[i] = h; g_Llo[i] = l;
}
__global__ void k_prepW(const float* __restrict__ W1, const float* __restrict__ W2) {
    int i = blockIdx.x * blockDim.x + threadIdx.x;
    if (i < 104 * 128) {
        int k = i >> 7, o = i & 127;
        bf16 h, l; split2(W1[i], h, l);
        g_W1h[o * 112 + k] = h; g_W1l[o * 112 + k] = l;
    } else if (i < 104 * 128 + 104 * 64) {
        int j = i - 104 * 128;
        int k = j >> 6, o = j & 63;
        bf16 h, l; split2(W2[j], h, l);
        g_W2h[o * 112 + k] = h; g_W2l[o * 112 + k] = l;
    }
}
__global__ void k_aspect(const float* __restrict__ inp,
                         const float* __restrict__ Wo, const float* __restrict__ bo,
                         const float* __restrict__ Wd, const float* __restrict__ bd,
                         const float* __restrict__ We, const float* __restrict__ be,
                         const float* __restrict__ Wi, const float* __restrict__ bi) {
    size_t i = (size_t)blockIdx.x * blockDim.x + threadIdx.x;
    if (i >= (size_t)NNODE * XCOLS) return;
    int n = (int)(i / XCOLS);
    int col = (int)(i - (size_t)n * XCOLS);
    int s = col / (BATCH * FEATD);
    int rem = col - s * (BATCH * FEATD);
    int b = rem / FEATD, f = rem - b * FEATD;
    const float* base = inp + (((size_t)(b * SEQ + s) * NNODE + n) * 21);
    int fo = f % 10;
    float acc;
    if (f < 10) {
        const int idx[5] = {2, 5, 8, 9, 12};
        acc = __ldg(bo + fo);
        #pragma unroll
        for (int j = 0; j < 5; j++) acc += __ldg(base + idx[j]) * __ldg(Wo + j * 10 + fo);
    } else if (f < 20) {
        const int idx[3] = {10, 14, 15};
        acc = __ldg(bd + fo);
        #pragma unroll
        for (int j = 0; j < 3; j++) acc += __ldg(base + idx[j]) * __ldg(Wd + j * 10 + fo);
    } else if (f < 30) {
        const int idx[2] = {13, 17};
        acc = __ldg(be + fo);
        #pragma unroll
        for (int j = 0; j < 2; j++) acc += __ldg(base + idx[j]) * __ldg(We + j * 10 + fo);
    } else {
        const int idx[2] = {19, 20};
        acc = __ldg(bi + fo);
        #pragma unroll
        for (int j = 0; j < 2; j++) acc += __ldg(base + idx[j]) * __ldg(Wi + j * 10 + fo);
    }
    g_xT[(size_t)n * XCOLS + col] = acc;
}

// ---------------- mma16816 ----------------
__device__ __forceinline__ void mma16816(float* d, const uint32_t* a, const uint32_t* b) {
    asm volatile(
        "mma.sync.aligned.m16n8k16.row.col.f32.bf16.bf16.f32 "
        "{%0,%1,%2,%3}, {%4,%5,%6,%7}, {%8,%9}, {%0,%1,%2,%3};"
        : "+f"(d[0]), "+f"(d[1]), "+f"(d[2]), "+f"(d[3])
        : "r"(a[0]), "r"(a[1]), "r"(a[2]), "r"(a[3]), "r"(b[0]), "r"(b[1]));
}

// ---------------- GEMM: C = A@B; A bf16 hi/lo K-major, B fp32 [k][n] split in-kernel ----------------
// cp.async double-buffered A, register-prefetched split B, ONE sync per chunk.
// smem (bf16 units): buffer stride 20480; Ah@0 Al@5120 Bh@10240 Bl@15360.
__device__ __forceinline__ void cpa_chunk(uint32_t smb, int p, const bf16* Ahi, const bf16* Alo,
                                          int m0, int k0, int tid) {
    #pragma unroll
    for (int it = 0; it < 4; it++) {
        int i = it * 256 + tid;
        int t = i >> 9, r = (i & 511) >> 2, s = i & 3;
        const bf16* src = (t ? Alo : Ahi) + (size_t)(m0 + r) * NPAD + k0 + s * 8;
        uint32_t dst = smb + p * 40960 + t * 10240 + r * 80 + s * 16;
        asm volatile("cp.async.cg.shared.global [%0], [%1], 16;" :: "r"(dst), "l"(src));
    }
}
__device__ __forceinline__ void storeB(bf16* sm, int p, const float* pb, int bn, int bk4) {
    uint32_t hw[8], lw[8];
    #pragma unroll
    for (int j = 0; j < 8; j++) {
        bf16 h0, l0, h1, l1;
        split2(pb[2 * j], h0, l0);
        split2(pb[2 * j + 1], h1, l1);
        hw[j] = packhl(h0, h1); lw[j] = packhl(l0, l1);
    }
    bf16* bh = sm + p * 20480 + 10240 + bn * 40 + bk4;
    bf16* bl = bh + 5120;
    *(uint4*)bh       = make_uint4(hw[0], hw[1], hw[2], hw[3]);
    *(uint4*)(bh + 8) = make_uint4(hw[4], hw[5], hw[6], hw[7]);
    *(uint4*)bl       = make_uint4(lw[0], lw[1], lw[2], lw[3]);
    *(uint4*)(bl + 8) = make_uint4(lw[4], lw[5], lw[6], lw[7]);
}
__global__ __launch_bounds__(256, 1)
void mma_gemm2(const bf16* __restrict__ Ahi, const bf16* __restrict__ Alo,
               const float* __restrict__ B, float* __restrict__ C, int ldc) {
    extern __shared__ bf16 sm[];
    uint32_t smb = smem_u32(sm);
    int tid = threadIdx.x, wid = tid >> 5, lane = tid & 31;
    int m0 = blockIdx.y * 128, n0 = blockIdx.x * 128;
    int wm = (wid & 1) * 64, wn = (wid >> 1) * 32;
    int qr = lane >> 2, qc = lane & 3;
    int bn = tid & 127, bk4 = (tid >> 7) * 16;
    const float* Bp = B + n0 + bn;
    float acc[4][4][4];
    #pragma unroll
    for (int a = 0; a < 4; a++)
        #pragma unroll
        for (int b = 0; b < 4; b++)
            #pragma unroll
            for (int c = 0; c < 4; c++) acc[a][b][c] = 0.f;
    float pb[16];

    // prologue: A(0) via cp.async; B(0) stored; B(1) in regs
    cpa_chunk(smb, 0, Ahi, Alo, m0, 0, tid);
    asm volatile("cp.async.commit_group;" ::: "memory");
    #pragma unroll
    for (int j = 0; j < 16; j++) pb[j] = Bp[(size_t)(bk4 + j) * ldc];
    storeB(sm, 0, pb, bn, bk4);
    #pragma unroll
    for (int j = 0; j < 16; j++) pb[j] = Bp[(size_t)(32 + bk4 + j) * ldc];
    asm volatile("cp.async.wait_group 0;" ::: "memory");
    __syncthreads();

    for (int c = 0; c < 32; c++) {
        int p = c & 1;
        if (c < 31) {
            cpa_chunk(smb, p ^ 1, Ahi, Alo, m0, (c + 1) * 32, tid);
            storeB(sm, p ^ 1, pb, bn, bk4);   // B(c+1) -> next buffer
        }
        asm volatile("cp.async.commit_group;" ::: "memory");
        if (c < 30) {
            int k0 = (c + 2) * 32;
            #pragma unroll
            for (int j = 0; j < 16; j++) pb[j] = Bp[(size_t)(k0 + bk4 + j) * ldc];
        }
        const bf16* sAh = sm + p * 20480;
        const bf16* sAl = sAh + 5120;
        const bf16* sBh = sAh + 10240;
        const bf16* sBl = sAh + 15360;
        #pragma unroll
        for (int ks = 0; ks < 32; ks += 16) {
            uint32_t ah[4][4], al[4][4], bh[4][2], bl[4][2];
            #pragma unroll
            for (int mi = 0; mi < 4; mi++) {
                int r = wm + mi * 16 + qr;
                ah[mi][0] = *(const uint32_t*)(sAh + r * 40 + ks + qc * 2);
                ah[mi][1] = *(const uint32_t*)(sAh + (r + 8) * 40 + ks + qc * 2);
                ah[mi][2] = *(const uint32_t*)(sAh + r * 40 + ks + 8 + qc * 2);
                ah[mi][3] = *(const uint32_t*)(sAh + (r + 8) * 40 + ks + 8 + qc * 2);
            }
            #pragma unroll
            for (int ni = 0; ni < 4; ni++) {
                int r = wn + ni * 8 + qr;
                bh[ni][0] = *(const uint32_t*)(sBh + r * 40 + ks + qc * 2);
                bh[ni][1] = *(const uint32_t*)(sBh + r * 40 + ks + 8 + qc * 2);
            }
            #pragma unroll
            for (int mi = 0; mi < 4; mi++)
                #pragma unroll
                for (int ni = 0; ni < 4; ni++) mma16816(acc[mi][ni], ah[mi], bh[ni]);
            #pragma unroll
            for (int mi = 0; mi < 4; mi++) {
                int r = wm + mi * 16 + qr;
                al[mi][0] = *(const uint32_t*)(sAl + r * 40 + ks + qc * 2);
                al[mi][1] = *(const uint32_t*)(sAl + (r + 8) * 40 + ks + qc * 2);
                al[mi][2] = *(const uint32_t*)(sAl + r * 40 + ks + 8 + qc * 2);
                al[mi][3] = *(const uint32_t*)(sAl + (r + 8) * 40 + ks + 8 + qc * 2);
            }
            #pragma unroll
            for (int mi = 0; mi < 4; mi++)
                #pragma unroll
                for (int ni = 0; ni < 4; ni++) mma16816(acc[mi][ni], al[mi], bh[ni]);
            #pragma unroll
            for (int ni = 0; ni < 4; ni++) {
                int r = wn + ni * 8 + qr;
                bl[ni][0] = *(const uint32_t*)(sBl + r * 40 + ks + qc * 2);
                bl[ni][1] = *(const uint32_t*)(sBl + r * 40 + ks + 8 + qc * 2);
            }
            #pragma unroll
            for (int mi = 0; mi < 4; mi++)
                #pragma unroll
                for (int ni = 0; ni < 4; ni++) mma16816(acc[mi][ni], ah[mi], bl[ni]);
        }
        asm volatile("cp.async.wait_group 0;" ::: "memory");
        __syncthreads();
    }
    #pragma unroll
    for (int mi = 0; mi < 4; mi++) {
        int r = m0 + wm + mi * 16 + qr;
        #pragma unroll
        for (int ni = 0; ni < 4; ni++) {
            int cc = n0 + wn + ni * 8 + qc * 2;
            *(float2*)(C + (size_t)r * ldc + cc)       = make_float2(acc[mi][ni][0], acc[mi][ni][1]);
            *(float2*)(C + (size_t)(r + 8) * ldc + cc) = make_float2(acc[mi][ni][2], acc[mi][ni][3]);
        }
    }
}

// ---------------- gate GEMM ----------------
__global__ __launch_bounds__(256, 1)
void k_gateG(const float* __restrict__ b1, int t) {
    extern __shared__ char dyn[];
    bf16* sAh = (bf16*)dyn;
    bf16* sAl = sAh + 128 * GP;
    bf16* sWh = sAl + 128 * GP;
    bf16* sWl = sWh + 128 * GP;
    float* sb = (float*)(sWl + 128 * GP);
    int tid = threadIdx.x, wid = tid >> 5, lane = tid & 31;
    int n0 = blockIdx.x * 4;
    for (int g = tid; g < 1024; g += 256) {   // zero A pad k=104..111
        int arr = g >> 9, rem = g & 511;
        int r = rem >> 2, k = 104 + (rem & 3) * 2;
        *(uint32_t*)((arr ? sAl : sAh) + r * GP + k) = 0;
    }
    for (int g = tid; g < 2560; g += 256) {   // Lx part (float2 -> packed u32)
        int ni = g / 640, rem = (g - ni * 640) * 2;
        float2 v = *(const float2*)(g_LxT + (size_t)(n0 + ni) * XCOLS + (size_t)t * 1280 + rem);
        int b = rem / 40, k = rem - b * 40;
        int row = ni * 32 + b;
        bf16 h0, l0, h1, l1; split2(v.x, h0, l0); split2(v.y, h1, l1);
        *(uint32_t*)(sAh + row * GP + k) = packhl(h0, h1);
        *(uint32_t*)(sAl + row * GP + k) = packhl(l0, l1);
    }
    for (int g = tid; g < 4096; g += 256) {   // Lh part
        int ni = g >> 10, rem = (g & 1023) * 2;
        float2 v = *(const float2*)(g_LhT + (n0 + ni) * HCOLS + rem);
        int row = ni * 32 + (rem >> 6), k = 40 + (rem & 63);
        bf16 h0, l0, h1, l1; split2(v.x, h0, l0); split2(v.y, h1, l1);
        *(uint32_t*)(sAh + row * GP + k) = packhl(h0, h1);
        *(uint32_t*)(sAl + row * GP + k) = packhl(l0, l1);
    }
    for (int g = tid; g < 3584; g += 256) {   // W copy (pre-split, uint4)
        int arr = g / 1792, rem = g - arr * 1792;
        int o = rem / 14, j = rem - o * 14;
        uint4 v = *(const uint4*)((arr ? g_W1l : g_W1h) + o * 112 + j * 8);
        *(uint4*)((arr ? sWl : sWh) + o * GP + j * 8) = v;
    }
    if (tid < 128) sb[tid] = b1[tid];
    __syncthreads();

    int wm = (wid & 1) * 64, wn = (wid >> 1) * 32;
    int qr = lane >> 2, qc = lane & 3;
    float acc[4][4][4];
    #pragma unroll
    for (int a = 0; a < 4; a++)
        #pragma unroll
        for (int b = 0; b < 4; b++)
            #pragma unroll
            for (int c = 0; c < 4; c++) acc[a][b][c] = 0.f;
    for (int ks = 0; ks < 112; ks += 16) {
        uint32_t ah[4][4], al[4][4], bh[4][2], bl[4][2];
        #pragma unroll
        for (int mi = 0; mi < 4; mi++) {
            int r = wm + mi * 16 + qr;
            ah[mi][0] = *(const uint32_t*)(sAh + r * GP + ks + qc * 2);
            ah[mi][1] = *(const uint32_t*)(sAh + (r + 8) * GP + ks + qc * 2);
            ah[mi][2] = *(const uint32_t*)(sAh + r * GP + ks + 8 + qc * 2);
            ah[mi][3] = *(const uint32_t*)(sAh + (r + 8) * GP + ks + 8 + qc * 2);
            al[mi][0] = *(const uint32_t*)(sAl + r * GP + ks + qc * 2);
            al[mi][1] = *(const uint32_t*)(sAl + (r + 8) * GP + ks + qc * 2);
            al[mi][2] = *(const uint32_t*)(sAl + r * GP + ks + 8 + qc * 2);
            al[mi][3] = *(const uint32_t*)(sAl + (r + 8) * GP + ks + 8 + qc * 2);
        }
        #pragma unroll
        for (int ni = 0; ni < 4; ni++) {
            int r = wn + ni * 8 + qr;
            bh[ni][0] = *(const uint32_t*)(sWh + r * GP + ks + qc * 2);
            bh[ni][1] = *(const uint32_t*)(sWh + r * GP + ks + 8 + qc * 2);
            bl[ni][0] = *(const uint32_t*)(sWl + r * GP + ks + qc * 2);
            bl[ni][1] = *(const uint32_t*)(sWl + r * GP + ks + 8 + qc * 2);
        }
        #pragma unroll
        for (int mi = 0; mi < 4; mi++)
            #pragma unroll
            for (int ni = 0; ni < 4; ni++) {
                mma16816(acc[mi][ni], ah[mi], bh[ni]);
                mma16816(acc[mi][ni], al[mi], bh[ni]);
                mma16816(acc[mi][ni], ah[mi], bl[ni]);
            }
    }
    #pragma unroll
    for (int mi = 0; mi < 4; mi++) {
        #pragma unroll
        for (int ni = 0; ni < 4; ni++) {
            int o = wn + ni * 8 + qc * 2;
            int half = o >> 6, ch = o & 63;
            #pragma unroll
            for (int hr = 0; hr < 2; hr++) {
                int row = wm + mi * 16 + qr + hr * 8;
                int n = n0 + (row >> 5), b = row & 31;
                float s0 = 1.f / (1.f + expf(-(acc[mi][ni][hr * 2]     + sb[o])));
                float s1 = 1.f / (1.f + expf(-(acc[mi][ni][hr * 2 + 1] + sb[o + 1])));
                if (n < 500) {
                    int idx = (2 * n + half) * HCOLS + b * 64 + ch;
                    float2 h2 = *(float2*)(g_hT + idx);
                    *(float2*)(g_rhT + idx) = make_float2(h2.x * s0, h2.y * s1);
                } else {
                    int idx = (2 * (n - 500) + half) * HCOLS + b * 64 + ch;
                    *(float2*)(g_uT + idx) = make_float2(s0, s1);
                }
            }
        }
    }
}

// ---------------- cand GEMM ----------------
__global__ __launch_bounds__(256, 1)
void k_candG(const float* __restrict__ b2, int t) {
    extern __shared__ char dyn[];
    bf16* sAh = (bf16*)dyn;
    bf16* sAl = sAh + 128 * GP;
    bf16* sWh = sAl + 128 * GP;
    bf16* sWl = sWh + 64 * GP;
    float* sb = (float*)(sWl + 64 * GP);
    int tid = threadIdx.x, wid = tid >> 5, lane = tid & 31;
    int n0 = blockIdx.x * 4;
    for (int g = tid; g < 1024; g += 256) {
        int arr = g >> 9, rem = g & 511;
        int r = rem >> 2, k = 104 + (rem & 3) * 2;
        *(uint32_t*)((arr ? sAl : sAh) + r * GP + k) = 0;
    }
    for (int g = tid; g < 2560; g += 256) {
        int ni = g / 640, rem = (g - ni * 640) * 2;
        float2 v = *(const float2*)(g_LxT + (size_t)(n0 + ni) * XCOLS + (size_t)t * 1280 + rem);
        int b = rem / 40, k = rem - b * 40;
        int row = ni * 32 + b;
        bf16 h0, l0, h1, l1; split2(v.x, h0, l0); split2(v.y, h1, l1);
        *(uint32_t*)(sAh + row * GP + k) = packhl(h0, h1);
        *(uint32_t*)(sAl + row * GP + k) = packhl(l0, l1);
    }
    for (int g = tid; g < 4096; g += 256) {
        int ni = g >> 10, rem = (g & 1023) * 2;
        float2 v = *(const float2*)(g_LrhT + (n0 + ni) * HCOLS + rem);
        int row = ni * 32 + (rem >> 6), k = 40 + (rem & 63);
        bf16 h0, l0, h1, l1; split2(v.x, h0, l0); split2(v.y, h1, l1);
        *(uint32_t*)(sAh + row * GP + k) = packhl(h0, h1);
        *(uint32_t*)(sAl + row * GP + k) = packhl(l0, l1);
    }
    for (int g = tid; g < 1792; g += 256) {
        int arr = g / 896, rem = g - arr * 896;
        int o = rem / 14, j = rem - o * 14;
        uint4 v = *(const uint4*)((arr ? g_W2l : g_W2h) + o * 112 + j * 8);
        *(uint4*)((arr ? sWl : sWh) + o * GP + j * 8) = v;
    }
    if (tid < 64) sb[tid] = b2[tid];
    __syncthreads();

    int wm = (wid & 3) * 32, wn = (wid >> 2) * 32;
    int qr = lane >> 2, qc = lane & 3;
    float acc[2][4][4];
    #pragma unroll
    for (int a = 0; a < 2; a++)
        #pragma unroll
        for (int b = 0; b < 4; b++)
            #pragma unroll
            for (int c = 0; c < 4; c++) acc[a][b][c] = 0.f;
    for (int ks = 0; ks < 112; ks += 16) {
        uint32_t ah[2][4], al[2][4], bh[4][2], bl[4][2];
        #pragma unroll
        for (int mi = 0; mi < 2; mi++) {
            int r = wm + mi * 16 + qr;
            ah[mi][0] = *(const uint32_t*)(sAh + r * GP + ks + qc * 2);
            ah[mi][1] = *(const uint32_t*)(sAh + (r + 8) * GP + ks + qc * 2);
            ah[mi][2] = *(const uint32_t*)(sAh + r * GP + ks + 8 + qc * 2);
            ah[mi][3] = *(const uint32_t*)(sAh + (r + 8) * GP + ks + 8 + qc * 2);
            al[mi][0] = *(const uint32_t*)(sAl + r * GP + ks + qc * 2);
            al[mi][1] = *(const uint32_t*)(sAl + (r + 8) * GP + ks + qc * 2);
            al[mi][2] = *(const uint32_t*)(sAl + r * GP + ks + 8 + qc * 2);
            al[mi][3] = *(const uint32_t*)(sAl + (r + 8) * GP + ks + 8 + qc * 2);
        }
        #pragma unroll
        for (int ni = 0; ni < 4; ni++) {
            int r = wn + ni * 8 + qr;
            bh[ni][0] = *(const uint32_t*)(sWh + r * GP + ks + qc * 2);
            bh[ni][1] = *(const uint32_t*)(sWh + r * GP + ks + 8 + qc * 2);
            bl[ni][0] = *(const uint32_t*)(sWl + r * GP + ks + qc * 2);
            bl[ni][1] = *(const uint32_t*)(sWl + r * GP + ks + 8 + qc * 2);
        }
        #pragma unroll
        for (int mi = 0; mi < 2; mi++)
            #pragma unroll
            for (int ni = 0; ni < 4; ni++) {
                mma16816(acc[mi][ni], ah[mi], bh[ni]);
                mma16816(acc[mi][ni], al[mi], bh[ni]);
                mma16816(acc[mi][ni], ah[mi], bl[ni]);
            }
    }
    #pragma unroll
    for (int mi = 0; mi < 2; mi++) {
        #pragma unroll
        for (int ni = 0; ni < 4; ni++) {
            int o = wn + ni * 8 + qc * 2;
            #pragma unroll
            for (int hr = 0; hr < 2; hr++) {
                int row = wm + mi * 16 + qr + hr * 8;
                int n = n0 + (row >> 5), b = row & 31;
                float c0 = tanhf(acc[mi][ni][hr * 2]     + sb[o]);
                float c1 = tanhf(acc[mi][ni][hr * 2 + 1] + sb[o + 1]);
                int idx = n * HCOLS + b * 64 + o;
                float2 u2 = *(float2*)(g_uT + idx);
                float2 h2 = *(float2*)(g_hT + idx);
                *(float2*)(g_hT + idx) =
                    make_float2(u2.x * h2.x + (1.f - u2.x) * c0,
                                u2.y * h2.y + (1.f - u2.y) * c1);
            }
        }
    }
}

__global__ void k_out(float* __restrict__ out) {
    int i = blockIdx.x * blockDim.x + threadIdx.x;
    if (i >= BATCH * NNODE * HID) return;
    int ch = i & (HID - 1);
    int n  = (i >> 6) % NNODE;
    int b  = i / (NNODE * HID);
    out[i] = g_hT[n * HCOLS + b * HID + ch];
}

// ---------------- launcher ----------------
extern "C" void kernel_launch(void* const* d_in, const int* in_sizes, int n_in,
                              void* d_out, int out_size) {
    const float* inp = (const float*)d_in[0];
    const float* adj = (const float*)d_in[1];
    const float* Wo = (const float*)d_in[2];  const float* bo = (const float*)d_in[3];
    const float* Wd = (const float*)d_in[4];  const float* bd = (const float*)d_in[5];
    const float* We = (const float*)d_in[6];  const float* be = (const float*)d_in[7];
    const float* Wi = (const float*)d_in[8];  const float* bi = (const float*)d_in[9];
    const float* W1 = (const float*)d_in[10]; const float* b1 = (const float*)d_in[11];
    const float* W2 = (const float*)d_in[12]; const float* b2 = (const float*)d_in[13];
    float* out = (float*)d_out;

    const int GEMM_SMEM = 2 * 40960;                              // 81920
    const int GATE_SMEM = 4 * 128 * GP * 2 + 128 * 4;             // 123392
    const int CAND_SMEM = (2 * 128 + 2 * 64) * GP * 2 + 64 * 4;   // 92416
    cudaFuncSetAttribute(mma_gemm2, cudaFuncAttributeMaxDynamicSharedMemorySize, GEMM_SMEM);
    cudaFuncSetAttribute(k_gateG, cudaFuncAttributeMaxDynamicSharedMemorySize, GATE_SMEM);
    cudaFuncSetAttribute(k_candG, cudaFuncAttributeMaxDynamicSharedMemorySize, CAND_SMEM);

    bf16 *Lhi, *Llo;
    float *xT, *LxT, *hT, *rhT, *LhT, *LrhT;
    cudaGetSymbolAddress((void**)&Lhi, g_Lhi);  cudaGetSymbolAddress((void**)&Llo, g_Llo);
    cudaGetSymbolAddress((void**)&xT, g_xT);    cudaGetSymbolAddress((void**)&LxT, g_LxT);
    cudaGetSymbolAddress((void**)&hT, g_hT);    cudaGetSymbolAddress((void**)&rhT, g_rhT);
    cudaGetSymbolAddress((void**)&LhT, g_LhT);  cudaGetSymbolAddress((void**)&LrhT, g_LrhT);

    k_zero_state<<<(NPAD * HCOLS + 255) / 256, 256>>>();
    k_zero_xpad<<<(int)(((size_t)(NPAD - NNODE) * XCOLS + 255) / 256), 256>>>();
    k_rowsum<<<NNODE, 256>>>(adj);
    k_buildL<<<(NPAD * NPAD) / 256, 256>>>(adj);
    k_prepW<<<78, 256>>>(W1, W2);
    k_aspect<<<(int)(((size_t)NNODE * XCOLS + 255) / 256), 256>>>(inp, Wo, bo, Wd, bd, We, be, Wi, bi);

    mma_gemm2<<<dim3(XCOLS / 128, NPAD / 128), 256, GEMM_SMEM>>>(Lhi, Llo, xT, LxT, XCOLS);

    for (int t = 0; t < SEQ; ++t) {
        mma_gemm2<<<dim3(HCOLS / 128, NPAD / 128), 256, GEMM_SMEM>>>(Lhi, Llo, hT, LhT, HCOLS);
        k_gateG<<<250, 256, GATE_SMEM>>>(b1, t);
        mma_gemm2<<<dim3(HCOLS / 128, NPAD / 128), 256, GEMM_SMEM>>>(Lhi, Llo, rhT, LrhT, HCOLS);
        k_candG<<<250, 256, CAND_SMEM>>>(b2, t);
    }

    k_out<<<(BATCH * NNODE * HID + 255) / 256, 256>>>(out);
}

// round 10
// speedup vs baseline: 4.6770x; 1.7278x over previous
#include <cuda_runtime.h>
#include <cuda_fp16.h>
#include <math.h>
#include <stdint.h>

#define NNODE 1000
#define NPAD  1024
#define BATCH 32
#define SEQ   48
#define HID   64
#define FEATD 40
#define XCOLS (SEQ*BATCH*FEATD)   // 61440
#define HCOLS (BATCH*HID)         // 2048
#define GP    120

// ---------------- static device scratch ----------------
__device__ float g_dis[NPAD];
__device__ __align__(128) __half g_L16[NPAD*NPAD];
__device__ __align__(128) float  g_xT  [(size_t)NPAD*XCOLS];
__device__ __align__(128) float  g_LxT [(size_t)NPAD*XCOLS];
__device__ __align__(128) float  g_hT  [NPAD*HCOLS];
__device__ __align__(128) float  g_rhT [NPAD*HCOLS];
__device__ __align__(128) float  g_uT  [NPAD*HCOLS];
__device__ __align__(128) float  g_LhT [NPAD*HCOLS];
__device__ __align__(128) float  g_LrhT[NPAD*HCOLS];
__device__ __align__(128) __half g_W1_16[128*112];  // zero-init covers k=104..111 pad
__device__ __align__(128) __half g_W2_16[64*112];

__device__ __forceinline__ uint32_t packh(float a, float b) {
    __half2 t = __floats2half2_rn(a, b);
    return *reinterpret_cast<uint32_t*>(&t);
}
__device__ __forceinline__ uint32_t smem_u32(const void* p) {
    uint32_t a;
    asm("{ .reg .u64 t; cvta.to.shared.u64 t, %1; cvt.u32.u64 %0, t; }" : "=r"(a) : "l"(p));
    return a;
}

// ---------------- prep ----------------
__global__ void k_zero_state() {
    int i = blockIdx.x * blockDim.x + threadIdx.x;
    if (i < NPAD * HCOLS) {
        g_hT[i] = 0.f;
        if (i >= NNODE * HCOLS) g_rhT[i] = 0.f;
    }
}
__global__ void k_zero_xpad() {
    size_t i = (size_t)blockIdx.x * blockDim.x + threadIdx.x;
    size_t tot = (size_t)(NPAD - NNODE) * XCOLS;
    if (i < tot) g_xT[(size_t)NNODE * XCOLS + i] = 0.f;
}
__global__ void k_rowsum(const float* __restrict__ adj) {
    int m = blockIdx.x, tid = threadIdx.x;
    float s = 0.f;
    for (int k = tid; k < NNODE; k += 256) s += adj[m * NNODE + k];
    __shared__ float sm[256];
    sm[tid] = s; __syncthreads();
    for (int st = 128; st > 0; st >>= 1) { if (tid < st) sm[tid] += sm[tid + st]; __syncthreads(); }
    if (tid == 0) g_dis[m] = rsqrtf(sm[0] + 1.0f);
}
__global__ void k_buildL(const float* __restrict__ adj) {
    int i = blockIdx.x * blockDim.x + threadIdx.x;
    if (i >= NPAD * NPAD) return;
    int m = i >> 10, n = i & (NPAD - 1);
    float v = 0.f;
    if (m < NNODE && n < NNODE)
        v = g_dis[m] * (adj[m * NNODE + n] + (m == n ? 1.f : 0.f)) * g_dis[n];
    g_L16[i] = __float2half(v);
}
__global__ void k_prepW(const float* __restrict__ W1, const float* __restrict__ W2) {
    int i = blockIdx.x * blockDim.x + threadIdx.x;
    if (i < 104 * 128) {
        int k = i >> 7, o = i & 127;
        g_W1_16[o * 112 + k] = __float2half(W1[i]);
    } else if (i < 104 * 128 + 104 * 64) {
        int j = i - 104 * 128;
        int k = j >> 6, o = j & 63;
        g_W2_16[o * 112 + k] = __float2half(W2[j]);
    }
}
__global__ void k_aspect(const float* __restrict__ inp,
                         const float* __restrict__ Wo, const float* __restrict__ bo,
                         const float* __restrict__ Wd, const float* __restrict__ bd,
                         const float* __restrict__ We, const float* __restrict__ be,
                         const float* __restrict__ Wi, const float* __restrict__ bi) {
    size_t i = (size_t)blockIdx.x * blockDim.x + threadIdx.x;
    if (i >= (size_t)NNODE * XCOLS) return;
    int n = (int)(i / XCOLS);
    int col = (int)(i - (size_t)n * XCOLS);
    int s = col / (BATCH * FEATD);
    int rem = col - s * (BATCH * FEATD);
    int b = rem / FEATD, f = rem - b * FEATD;
    const float* base = inp + (((size_t)(b * SEQ + s) * NNODE + n) * 21);
    int fo = f % 10;
    float acc;
    if (f < 10) {
        const int idx[5] = {2, 5, 8, 9, 12};
        acc = __ldg(bo + fo);
        #pragma unroll
        for (int j = 0; j < 5; j++) acc += __ldg(base + idx[j]) * __ldg(Wo + j * 10 + fo);
    } else if (f < 20) {
        const int idx[3] = {10, 14, 15};
        acc = __ldg(bd + fo);
        #pragma unroll
        for (int j = 0; j < 3; j++) acc += __ldg(base + idx[j]) * __ldg(Wd + j * 10 + fo);
    } else if (f < 30) {
        const int idx[2] = {13, 17};
        acc = __ldg(be + fo);
        #pragma unroll
        for (int j = 0; j < 2; j++) acc += __ldg(base + idx[j]) * __ldg(We + j * 10 + fo);
    } else {
        const int idx[2] = {19, 20};
        acc = __ldg(bi + fo);
        #pragma unroll
        for (int j = 0; j < 2; j++) acc += __ldg(base + idx[j]) * __ldg(Wi + j * 10 + fo);
    }
    g_xT[(size_t)n * XCOLS + col] = acc;
}

// ---------------- mma16816 fp16 ----------------
__device__ __forceinline__ void mma16816(float* d, const uint32_t* a, const uint32_t* b) {
    asm volatile(
        "mma.sync.aligned.m16n8k16.row.col.f32.f16.f16.f32 "
        "{%0,%1,%2,%3}, {%4,%5,%6,%7}, {%8,%9}, {%0,%1,%2,%3};"
        : "+f"(d[0]), "+f"(d[1]), "+f"(d[2]), "+f"(d[3])
        : "r"(a[0]), "r"(a[1]), "r"(a[2]), "r"(a[3]), "r"(b[0]), "r"(b[1]));
}

// ---------------- GEMM: C = A@B; A fp16 K-major, B fp32 [k][n] converted in-kernel ----------------
// cp.async double-buffered A, register-prefetched B, ONE sync per chunk.
// smem (halves): buffer stride 10240; A@0 (128x40), B@5120 (128x40).
__device__ __forceinline__ void cpa_chunkH(uint32_t smb, int p, const __half* A,
                                           int m0, int k0, int tid) {
    #pragma unroll
    for (int it = 0; it < 2; it++) {
        int i = it * 256 + tid;
        int r = i >> 2, s = i & 3;
        const __half* src = A + (size_t)(m0 + r) * NPAD + k0 + s * 8;
        uint32_t dst = smb + p * 20480 + r * 80 + s * 16;
        asm volatile("cp.async.cg.shared.global [%0], [%1], 16;" :: "r"(dst), "l"(src));
    }
}
__device__ __forceinline__ void storeBH(__half* sm, int p, const float* pb, int bn, int bk4) {
    uint32_t w[8];
    #pragma unroll
    for (int j = 0; j < 8; j++) w[j] = packh(pb[2 * j], pb[2 * j + 1]);
    __half* b = sm + p * 10240 + 5120 + bn * 40 + bk4;
    *(uint4*)b       = make_uint4(w[0], w[1], w[2], w[3]);
    *(uint4*)(b + 8) = make_uint4(w[4], w[5], w[6], w[7]);
}
__global__ __launch_bounds__(256)
void mma_gemmH(const __half* __restrict__ A, const float* __restrict__ B,
               float* __restrict__ C, int ldc) {
    extern __shared__ __half sm[];
    uint32_t smb = smem_u32(sm);
    int tid = threadIdx.x, wid = tid >> 5, lane = tid & 31;
    int m0 = blockIdx.y * 128, n0 = blockIdx.x * 128;
    int wm = (wid & 1) * 64, wn = (wid >> 1) * 32;
    int qr = lane >> 2, qc = lane & 3;
    int bn = tid & 127, bk4 = (tid >> 7) * 16;
    const float* Bp = B + n0 + bn;
    float acc[4][4][4];
    #pragma unroll
    for (int a = 0; a < 4; a++)
        #pragma unroll
        for (int b = 0; b < 4; b++)
            #pragma unroll
            for (int c = 0; c < 4; c++) acc[a][b][c] = 0.f;
    float pb[16];

    // prologue: A(0) via cp.async; B(0) stored; B(1) in regs
    cpa_chunkH(smb, 0, A, m0, 0, tid);
    asm volatile("cp.async.commit_group;" ::: "memory");
    #pragma unroll
    for (int j = 0; j < 16; j++) pb[j] = Bp[(size_t)(bk4 + j) * ldc];
    storeBH(sm, 0, pb, bn, bk4);
    #pragma unroll
    for (int j = 0; j < 16; j++) pb[j] = Bp[(size_t)(32 + bk4 + j) * ldc];
    asm volatile("cp.async.wait_group 0;" ::: "memory");
    __syncthreads();

    for (int c = 0; c < 32; c++) {
        int p = c & 1;
        if (c < 31) {
            cpa_chunkH(smb, p ^ 1, A, m0, (c + 1) * 32, tid);
            storeBH(sm, p ^ 1, pb, bn, bk4);
        }
        asm volatile("cp.async.commit_group;" ::: "memory");
        if (c < 30) {
            int k0 = (c + 2) * 32;
            #pragma unroll
            for (int j = 0; j < 16; j++) pb[j] = Bp[(size_t)(k0 + bk4 + j) * ldc];
        }
        const __half* sA = sm + p * 10240;
        const __half* sB = sA + 5120;
        #pragma unroll
        for (int ks = 0; ks < 32; ks += 16) {
            uint32_t ah[4][4], bh[4][2];
            #pragma unroll
            for (int mi = 0; mi < 4; mi++) {
                int r = wm + mi * 16 + qr;
                ah[mi][0] = *(const uint32_t*)(sA + r * 40 + ks + qc * 2);
                ah[mi][1] = *(const uint32_t*)(sA + (r + 8) * 40 + ks + qc * 2);
                ah[mi][2] = *(const uint32_t*)(sA + r * 40 + ks + 8 + qc * 2);
                ah[mi][3] = *(const uint32_t*)(sA + (r + 8) * 40 + ks + 8 + qc * 2);
            }
            #pragma unroll
            for (int ni = 0; ni < 4; ni++) {
                int r = wn + ni * 8 + qr;
                bh[ni][0] = *(const uint32_t*)(sB + r * 40 + ks + qc * 2);
                bh[ni][1] = *(const uint32_t*)(sB + r * 40 + ks + 8 + qc * 2);
            }
            #pragma unroll
            for (int mi = 0; mi < 4; mi++)
                #pragma unroll
                for (int ni = 0; ni < 4; ni++) mma16816(acc[mi][ni], ah[mi], bh[ni]);
        }
        asm volatile("cp.async.wait_group 0;" ::: "memory");
        __syncthreads();
    }
    #pragma unroll
    for (int mi = 0; mi < 4; mi++) {
        int r = m0 + wm + mi * 16 + qr;
        #pragma unroll
        for (int ni = 0; ni < 4; ni++) {
            int cc = n0 + wn + ni * 8 + qc * 2;
            *(float2*)(C + (size_t)r * ldc + cc)       = make_float2(acc[mi][ni][0], acc[mi][ni][1]);
            *(float2*)(C + (size_t)(r + 8) * ldc + cc) = make_float2(acc[mi][ni][2], acc[mi][ni][3]);
        }
    }
}

// ---------------- gate GEMM: rows n*32+b, K=[Lx(40)|Lh(64)|pad8], N=128; sigmoid + chunk remap ----------------
__global__ __launch_bounds__(256)
void k_gateG(const float* __restrict__ b1, int t) {
    extern __shared__ char dyn[];
    __half* sA = (__half*)dyn;
    __half* sW = sA + 128 * GP;
    float* sb = (float*)(sW + 128 * GP);
    int tid = threadIdx.x, wid = tid >> 5, lane = tid & 31;
    int n0 = blockIdx.x * 4;
    for (int g = tid; g < 512; g += 256) {   // zero A pad k=104..111
        int r = g >> 2, k = 104 + (g & 3) * 2;
        *(uint32_t*)(sA + r * GP + k) = 0;
    }
    for (int g = tid; g < 2560; g += 256) {  // Lx
        int ni = g / 640, rem = (g - ni * 640) * 2;
        float2 v = *(const float2*)(g_LxT + (size_t)(n0 + ni) * XCOLS + (size_t)t * 1280 + rem);
        int b = rem / 40, k = rem - b * 40;
        *(uint32_t*)(sA + (ni * 32 + b) * GP + k) = packh(v.x, v.y);
    }
    for (int g = tid; g < 4096; g += 256) {  // Lh
        int ni = g >> 10, rem = (g & 1023) * 2;
        float2 v = *(const float2*)(g_LhT + (n0 + ni) * HCOLS + rem);
        int row = ni * 32 + (rem >> 6), k = 40 + (rem & 63);
        *(uint32_t*)(sA + row * GP + k) = packh(v.x, v.y);
    }
    for (int g = tid; g < 1792; g += 256) {  // W (pre-split fp16, uint4)
        int o = g / 14, j = g - o * 14;
        uint4 v = *(const uint4*)(g_W1_16 + o * 112 + j * 8);
        *(uint4*)(sW + o * GP + j * 8) = v;
    }
    if (tid < 128) sb[tid] = b1[tid];
    __syncthreads();

    int wm = (wid & 1) * 64, wn = (wid >> 1) * 32;
    int qr = lane >> 2, qc = lane & 3;
    float acc[4][4][4];
    #pragma unroll
    for (int a = 0; a < 4; a++)
        #pragma unroll
        for (int b = 0; b < 4; b++)
            #pragma unroll
            for (int c = 0; c < 4; c++) acc[a][b][c] = 0.f;
    for (int ks = 0; ks < 112; ks += 16) {
        uint32_t ah[4][4], bh[4][2];
        #pragma unroll
        for (int mi = 0; mi < 4; mi++) {
            int r = wm + mi * 16 + qr;
            ah[mi][0] = *(const uint32_t*)(sA + r * GP + ks + qc * 2);
            ah[mi][1] = *(const uint32_t*)(sA + (r + 8) * GP + ks + qc * 2);
            ah[mi][2] = *(const uint32_t*)(sA + r * GP + ks + 8 + qc * 2);
            ah[mi][3] = *(const uint32_t*)(sA + (r + 8) * GP + ks + 8 + qc * 2);
        }
        #pragma unroll
        for (int ni = 0; ni < 4; ni++) {
            int r = wn + ni * 8 + qr;
            bh[ni][0] = *(const uint32_t*)(sW + r * GP + ks + qc * 2);
            bh[ni][1] = *(const uint32_t*)(sW + r * GP + ks + 8 + qc * 2);
        }
        #pragma unroll
        for (int mi = 0; mi < 4; mi++)
            #pragma unroll
            for (int ni = 0; ni < 4; ni++) mma16816(acc[mi][ni], ah[mi], bh[ni]);
    }
    #pragma unroll
    for (int mi = 0; mi < 4; mi++) {
        #pragma unroll
        for (int ni = 0; ni < 4; ni++) {
            int o = wn + ni * 8 + qc * 2;
            int half_ = o >> 6, ch = o & 63;
            #pragma unroll
            for (int hr = 0; hr < 2; hr++) {
                int row = wm + mi * 16 + qr + hr * 8;
                int n = n0 + (row >> 5), b = row & 31;
                float s0 = 1.f / (1.f + expf(-(acc[mi][ni][hr * 2]     + sb[o])));
                float s1 = 1.f / (1.f + expf(-(acc[mi][ni][hr * 2 + 1] + sb[o + 1])));
                if (n < 500) {
                    int idx = (2 * n + half_) * HCOLS + b * 64 + ch;
                    float2 h2 = *(float2*)(g_hT + idx);
                    *(float2*)(g_rhT + idx) = make_float2(h2.x * s0, h2.y * s1);
                } else {
                    int idx = (2 * (n - 500) + half_) * HCOLS + b * 64 + ch;
                    *(float2*)(g_uT + idx) = make_float2(s0, s1);
                }
            }
        }
    }
}

// ---------------- cand GEMM: K=[Lx|Lrh], N=64; tanh + GRU update ----------------
__global__ __launch_bounds__(256)
void k_candG(const float* __restrict__ b2, int t) {
    extern __shared__ char dyn[];
    __half* sA = (__half*)dyn;
    __half* sW = sA + 128 * GP;
    float* sb = (float*)(sW + 64 * GP);
    int tid = threadIdx.x, wid = tid >> 5, lane = tid & 31;
    int n0 = blockIdx.x * 4;
    for (int g = tid; g < 512; g += 256) {
        int r = g >> 2, k = 104 + (g & 3) * 2;
        *(uint32_t*)(sA + r * GP + k) = 0;
    }
    for (int g = tid; g < 2560; g += 256) {
        int ni = g / 640, rem = (g - ni * 640) * 2;
        float2 v = *(const float2*)(g_LxT + (size_t)(n0 + ni) * XCOLS + (size_t)t * 1280 + rem);
        int b = rem / 40, k = rem - b * 40;
        *(uint32_t*)(sA + (ni * 32 + b) * GP + k) = packh(v.x, v.y);
    }
    for (int g = tid; g < 4096; g += 256) {
        int ni = g >> 10, rem = (g & 1023) * 2;
        float2 v = *(const float2*)(g_LrhT + (n0 + ni) * HCOLS + rem);
        int row = ni * 32 + (rem >> 6), k = 40 + (rem & 63);
        *(uint32_t*)(sA + row * GP + k) = packh(v.x, v.y);
    }
    for (int g = tid; g < 896; g += 256) {
        int o = g / 14, j = g - o * 14;
        uint4 v = *(const uint4*)(g_W2_16 + o * 112 + j * 8);
        *(uint4*)(sW + o * GP + j * 8) = v;
    }
    if (tid < 64) sb[tid] = b2[tid];
    __syncthreads();

    int wm = (wid & 3) * 32, wn = (wid >> 2) * 32;
    int qr = lane >> 2, qc = lane & 3;
    float acc[2][4][4];
    #pragma unroll
    for (int a = 0; a < 2; a++)
        #pragma unroll
        for (int b = 0; b < 4; b++)
            #pragma unroll
            for (int c = 0; c < 4; c++) acc[a][b][c] = 0.f;
    for (int ks = 0; ks < 112; ks += 16) {
        uint32_t ah[2][4], bh[4][2];
        #pragma unroll
        for (int mi = 0; mi < 2; mi++) {
            int r = wm + mi * 16 + qr;
            ah[mi][0] = *(const uint32_t*)(sA + r * GP + ks + qc * 2);
            ah[mi][1] = *(const uint32_t*)(sA + (r + 8) * GP + ks + qc * 2);
            ah[mi][2] = *(const uint32_t*)(sA + r * GP + ks + 8 + qc * 2);
            ah[mi][3] = *(const uint32_t*)(sA + (r + 8) * GP + ks + 8 + qc * 2);
        }
        #pragma unroll
        for (int ni = 0; ni < 4; ni++) {
            int r = wn + ni * 8 + qr;
            bh[ni][0] = *(const uint32_t*)(sW + r * GP + ks + qc * 2);
            bh[ni][1] = *(const uint32_t*)(sW + r * GP + ks + 8 + qc * 2);
        }
        #pragma unroll
        for (int mi = 0; mi < 2; mi++)
            #pragma unroll
            for (int ni = 0; ni < 4; ni++) mma16816(acc[mi][ni], ah[mi], bh[ni]);
    }
    #pragma unroll
    for (int mi = 0; mi < 2; mi++) {
        #pragma unroll
        for (int ni = 0; ni < 4; ni++) {
            int o = wn + ni * 8 + qc * 2;
            #pragma unroll
            for (int hr = 0; hr < 2; hr++) {
                int row = wm + mi * 16 + qr + hr * 8;
                int n = n0 + (row >> 5), b = row & 31;
                float c0 = tanhf(acc[mi][ni][hr * 2]     + sb[o]);
                float c1 = tanhf(acc[mi][ni][hr * 2 + 1] + sb[o + 1]);
                int idx = n * HCOLS + b * 64 + o;
                float2 u2 = *(float2*)(g_uT + idx);
                float2 h2 = *(float2*)(g_hT + idx);
                *(float2*)(g_hT + idx) =
                    make_float2(u2.x * h2.x + (1.f - u2.x) * c0,
                                u2.y * h2.y + (1.f - u2.y) * c1);
            }
        }
    }
}

__global__ void k_out(float* __restrict__ out) {
    int i = blockIdx.x * blockDim.x + threadIdx.x;
    if (i >= BATCH * NNODE * HID) return;
    int ch = i & (HID - 1);
    int n  = (i >> 6) % NNODE;
    int b  = i / (NNODE * HID);
    out[i] = g_hT[n * HCOLS + b * HID + ch];
}

// ---------------- launcher ----------------
extern "C" void kernel_launch(void* const* d_in, const int* in_sizes, int n_in,
                              void* d_out, int out_size) {
    const float* inp = (const float*)d_in[0];
    const float* adj = (const float*)d_in[1];
    const float* Wo = (const float*)d_in[2];  const float* bo = (const float*)d_in[3];
    const float* Wd = (const float*)d_in[4];  const float* bd = (const float*)d_in[5];
    const float* We = (const float*)d_in[6];  const float* be = (const float*)d_in[7];
    const float* Wi = (const float*)d_in[8];  const float* bi = (const float*)d_in[9];
    const float* W1 = (const float*)d_in[10]; const float* b1 = (const float*)d_in[11];
    const float* W2 = (const float*)d_in[12]; const float* b2 = (const float*)d_in[13];
    float* out = (float*)d_out;

    const int GEMM_SMEM = 2 * 20480;                          // 40960
    const int GATE_SMEM = 2 * 128 * GP * 2 + 128 * 4;         // 61952
    const int CAND_SMEM = (128 + 64) * GP * 2 + 64 * 4;       // 46336
    cudaFuncSetAttribute(mma_gemmH, cudaFuncAttributeMaxDynamicSharedMemorySize, GEMM_SMEM);
    cudaFuncSetAttribute(k_gateG, cudaFuncAttributeMaxDynamicSharedMemorySize, GATE_SMEM);
    cudaFuncSetAttribute(k_candG, cudaFuncAttributeMaxDynamicSharedMemorySize, CAND_SMEM);

    __half* L16;
    float *xT, *LxT, *hT, *rhT, *LhT, *LrhT;
    cudaGetSymbolAddress((void**)&L16, g_L16);
    cudaGetSymbolAddress((void**)&xT, g_xT);    cudaGetSymbolAddress((void**)&LxT, g_LxT);
    cudaGetSymbolAddress((void**)&hT, g_hT);    cudaGetSymbolAddress((void**)&rhT, g_rhT);
    cudaGetSymbolAddress((void**)&LhT, g_LhT);  cudaGetSymbolAddress((void**)&LrhT, g_LrhT);

    k_zero_state<<<(NPAD * HCOLS + 255) / 256, 256>>>();
    k_zero_xpad<<<(int)(((size_t)(NPAD - NNODE) * XCOLS + 255) / 256), 256>>>();
    k_rowsum<<<NNODE, 256>>>(adj);
    k_buildL<<<(NPAD * NPAD) / 256, 256>>>(adj);
    k_prepW<<<78, 256>>>(W1, W2);
    k_aspect<<<(int)(((size_t)NNODE * XCOLS + 255) / 256), 256>>>(inp, Wo, bo, Wd, bd, We, be, Wi, bi);

    mma_gemmH<<<dim3(XCOLS / 128, NPAD / 128), 256, GEMM_SMEM>>>(L16, xT, LxT, XCOLS);

    for (int t = 0; t < SEQ; ++t) {
        mma_gemmH<<<dim3(HCOLS / 128, NPAD / 128), 256, GEMM_SMEM>>>(L16, hT, LhT, HCOLS);
        k_gateG<<<250, 256, GATE_SMEM>>>(b1, t);
        mma_gemmH<<<dim3(HCOLS / 128, NPAD / 128), 256, GEMM_SMEM>>>(L16, rhT, LrhT, HCOLS);
        k_candG<<<250, 256, CAND_SMEM>>>(b2, t);
    }

    k_out<<<(BATCH * NNODE * HID + 255) / 256, 256>>>(out);
}